// round 1
// baseline (speedup 1.0000x reference)
#include <cuda_runtime.h>
#include <math.h>

#define B_  8
#define S_  4096
#define T_  77
#define C_  1280
#define CE_ 2048
#define H_  20
#define D_  64
#define HD_ 1280
#define KTOK_ 12
#define KPOS_ 1229
#define SCHUNK_ (S_/128)   // 32

#define SCALE_ 0.125f
#define STRENGTH_ 0.5f
#define ALPHA_ 0.7f
#define WINJ_ 0.25f        // FIW * STRENGTH

// ---------------- scratch (device globals; no allocations) ----------------
__device__ float g_q[(size_t)B_*S_*HD_];          // 168 MB
__device__ float g_k[B_*T_*HD_];
__device__ float g_v[B_*T_*HD_];
__device__ float g_k2[B_*T_*HD_];
__device__ float g_v2[B_*T_*HD_];
__device__ float g_probs[(size_t)B_*H_*S_*T_];    // 202 MB
__device__ float g_tokpart[B_*H_*SCHUNK_*T_];
__device__ float g_tokscores[B_*T_];
__device__ int   g_tokmask[B_*T_];
__device__ float g_posscores[B_*S_];
__device__ int   g_posmask[B_*S_];
__device__ float g_ctx[(size_t)B_*S_*HD_];        // 168 MB
__device__ float g_ctxsum[(size_t)S_*HD_];

// ---------------- classic fp32 SGEMM 128x128x8, 8x8 per thread ----------------
template<int EPI>
__global__ __launch_bounds__(256) void sgemm_k(
    const float* __restrict__ A, const float* __restrict__ Bm, float* __restrict__ Cm,
    int M, int N, int K,
    const float* __restrict__ bias, const float* __restrict__ resid)
{
    __shared__ float As[8][128];
    __shared__ float Bs[8][128];
    const int tid  = threadIdx.x;
    const int cRow = blockIdx.y;
    const int cCol = blockIdx.x;
    const int aRow = tid >> 1;
    const int aCol = (tid & 1) << 2;
    const int bRow = tid >> 5;
    const int bCol = (tid & 31) << 2;
    const int tRow = (tid >> 4) << 3;
    const int tCol = (tid & 15) << 3;

    float acc[8][8];
#pragma unroll
    for (int i = 0; i < 8; i++) {
#pragma unroll
        for (int j = 0; j < 8; j++) acc[i][j] = 0.f;
    }

    const int rowA = cRow * 128 + aRow;
    const bool aOk = rowA < M;
    const float* Aptr = A + (size_t)rowA * K + aCol;
    const float* Bptr = Bm + (size_t)bRow * N + cCol * 128 + bCol;

    for (int k0 = 0; k0 < K; k0 += 8) {
        float4 av = aOk ? *(const float4*)(Aptr + k0) : make_float4(0.f, 0.f, 0.f, 0.f);
        As[aCol + 0][aRow] = av.x;
        As[aCol + 1][aRow] = av.y;
        As[aCol + 2][aRow] = av.z;
        As[aCol + 3][aRow] = av.w;
        float4 bv = *(const float4*)(Bptr + (size_t)k0 * N);
        *(float4*)&Bs[bRow][bCol] = bv;
        __syncthreads();
#pragma unroll
        for (int kk = 0; kk < 8; kk++) {
            float4 a0 = *(const float4*)&As[kk][tRow];
            float4 a1 = *(const float4*)&As[kk][tRow + 4];
            float4 b0 = *(const float4*)&Bs[kk][tCol];
            float4 b1 = *(const float4*)&Bs[kk][tCol + 4];
            float ra[8] = {a0.x, a0.y, a0.z, a0.w, a1.x, a1.y, a1.z, a1.w};
            float rb[8] = {b0.x, b0.y, b0.z, b0.w, b1.x, b1.y, b1.z, b1.w};
#pragma unroll
            for (int i = 0; i < 8; i++) {
#pragma unroll
                for (int j = 0; j < 8; j++) acc[i][j] += ra[i] * rb[j];
            }
        }
        __syncthreads();
    }

#pragma unroll
    for (int i = 0; i < 8; i++) {
        int m = cRow * 128 + tRow + i;
        if (m < M) {
            size_t off = (size_t)m * N + cCol * 128 + tCol;
#pragma unroll
            for (int j = 0; j < 8; j += 4) {
                float4 o;
                o.x = acc[i][j]; o.y = acc[i][j + 1]; o.z = acc[i][j + 2]; o.w = acc[i][j + 3];
                if (EPI) {
                    int n = cCol * 128 + tCol + j;
                    float4 r = *(const float4*)(resid + off + j);
                    o.x += bias[n]     + r.x;
                    o.y += bias[n + 1] + r.y;
                    o.z += bias[n + 2] + r.z;
                    o.w += bias[n + 3] + r.w;
                }
                *(float4*)(Cm + off + j) = o;
            }
        }
    }
}

// ---------------- attention pass 1: probs + per-block token partials ----------------
__global__ __launch_bounds__(128) void attn1_k(
    const float* __restrict__ q, const float* __restrict__ kk,
    float* __restrict__ probs, float* __restrict__ tokpart)
{
    const int b = blockIdx.z, h = blockIdx.y;
    const int tid = threadIdx.x;
    const int s = blockIdx.x * 128 + tid;
    __shared__ float ks[T_ * D_];
    __shared__ float tpw[4][T_];
    const int w = tid >> 5, lane = tid & 31;

    for (int i = tid; i < T_ * D_; i += 128) {
        int t = i >> 6, d = i & 63;
        ks[i] = kk[((size_t)(b * T_ + t)) * HD_ + h * D_ + d];
    }
    for (int i = lane; i < T_; i += 32) tpw[w][i] = 0.f;
    __syncthreads();

    float qreg[D_];
    const float* qp = q + ((size_t)(b * S_) + s) * HD_ + h * D_;
#pragma unroll
    for (int d = 0; d < D_; d++) qreg[d] = qp[d];

    float m = -1e30f, ssum = 0.f;
    for (int t = 0; t < T_; t++) {
        const float* kp = &ks[t * D_];
        float l = 0.f;
#pragma unroll
        for (int d = 0; d < D_; d++) l += qreg[d] * kp[d];
        l *= SCALE_;
        float mn = fmaxf(m, l);
        ssum = ssum * expf(m - mn) + expf(l - mn);
        m = mn;
    }
    const float inv = 1.f / ssum;
    const size_t pbase = (((size_t)(b * H_) + h) * S_ + s) * T_;
    for (int t = 0; t < T_; t++) {
        const float* kp = &ks[t * D_];
        float l = 0.f;
#pragma unroll
        for (int d = 0; d < D_; d++) l += qreg[d] * kp[d];
        float p = expf(l * SCALE_ - m) * inv;
        probs[pbase + t] = p;
        float ps = p;
#pragma unroll
        for (int o = 16; o; o >>= 1) ps += __shfl_xor_sync(0xffffffffu, ps, o);
        if (lane == 0) tpw[w][t] += ps;
    }
    __syncthreads();
    if (tid < T_) {
        int lin = (b * H_ + h) * SCHUNK_ + blockIdx.x;
        tokpart[(size_t)lin * T_ + tid] = tpw[0][tid] + tpw[1][tid] + tpw[2][tid] + tpw[3][tid];
    }
}

// ---------------- token score reduce + top-k ----------------
__global__ void tok_reduce_k(const float* __restrict__ tokpart, float* __restrict__ scores)
{
    int idx = blockIdx.x * blockDim.x + threadIdx.x;
    if (idx >= B_ * T_) return;
    int b = idx / T_, t = idx % T_;
    float sum = 0.f;
    for (int h = 0; h < H_; h++)
        for (int c = 0; c < SCHUNK_; c++)
            sum += tokpart[(size_t)((b * H_ + h) * SCHUNK_ + c) * T_ + t];
    scores[idx] = sum * (1.f / (float)(H_ * S_));
}

__global__ void tok_topk_k(const float* __restrict__ scores, int* __restrict__ mask)
{
    int b = blockIdx.x, tid = threadIdx.x;
    __shared__ float sc[T_];
    if (tid < T_) sc[tid] = scores[b * T_ + tid];
    __syncthreads();
    if (tid < T_) {
        float v = sc[tid];
        int rank = 0;
        for (int j = 0; j < T_; j++) {
            float u = sc[j];
            rank += (int)((u > v) || (u == v && j < tid));
        }
        mask[b * T_ + tid] = (rank < KTOK_) ? 1 : 0;
    }
}

// ---------------- position scores + top-k ----------------
__global__ __launch_bounds__(256) void pos_scores_k(
    const float* __restrict__ probs, const int* __restrict__ tokmask, float* __restrict__ out)
{
    const int b = blockIdx.y;
    const int s = blockIdx.x * 256 + threadIdx.x;
    __shared__ float msk[T_];
    if (threadIdx.x < T_) msk[threadIdx.x] = (float)tokmask[b * T_ + threadIdx.x];
    __syncthreads();
    float sum = 0.f;
    for (int h = 0; h < H_; h++) {
        const float* p = probs + (((size_t)(b * H_) + h) * S_ + s) * T_;
        for (int t = 0; t < T_; t++) sum += p[t] * msk[t];
    }
    out[b * S_ + s] = sum * (1.f / (float)H_);
}

__global__ __launch_bounds__(256) void pos_topk_k(const float* __restrict__ scores, int* __restrict__ mask)
{
    const int b = blockIdx.y;
    __shared__ float sc[S_];
    for (int i = threadIdx.x; i < S_; i += 256) sc[i] = scores[b * S_ + i];
    __syncthreads();
    const int i = blockIdx.x * 256 + threadIdx.x;
    float v = sc[i];
    int rank = 0;
    for (int j = 0; j < S_; j++) {
        float u = sc[j];
        rank += (int)((u > v) || (u == v && j < i));
    }
    mask[b * S_ + i] = (rank < KPOS_) ? 1 : 0;
}

// ---------------- cross-frame K/V mixing ----------------
__global__ void kvmix_k(const float* __restrict__ kin, const float* __restrict__ vin,
                        const int* __restrict__ tokmask,
                        float* __restrict__ k2, float* __restrict__ v2)
{
    int idx = blockIdx.x * blockDim.x + threadIdx.x;
    if (idx >= T_ * HD_) return;
    int t = idx / HD_;
    int c = idx % HD_;
    float kv[B_], vv[B_];
    float ksum = 0.f, vsum = 0.f;
#pragma unroll
    for (int b = 0; b < B_; b++) {
        size_t off = ((size_t)(b * T_) + t) * HD_ + c;
        kv[b] = kin[off];
        vv[b] = vin[off];
        ksum += kv[b];
        vsum += vv[b];
    }
#pragma unroll
    for (int b = 0; b < B_; b++) {
        float tm = tokmask[b * T_ + t] ? STRENGTH_ : 0.f;
        size_t off = ((size_t)(b * T_) + t) * HD_ + c;
        float x  = kv[b];
        float mo = (ksum - x) * (1.f / (float)(B_ - 1));
        float mixed = ALPHA_ * x + (1.f - ALPHA_) * mo;
        k2[off] = x + tm * (mixed - x);
        x  = vv[b];
        mo = (vsum - x) * (1.f / (float)(B_ - 1));
        mixed = ALPHA_ * x + (1.f - ALPHA_) * mo;
        v2[off] = x + tm * (mixed - x);
    }
}

// ---------------- attention pass 2: flash-style softmax + context ----------------
__global__ __launch_bounds__(128) void attn2_k(
    const float* __restrict__ q, const float* __restrict__ k2,
    const float* __restrict__ v2, float* __restrict__ ctx)
{
    const int b = blockIdx.z, h = blockIdx.y;
    const int tid = threadIdx.x;
    const int s = blockIdx.x * 128 + tid;
    __shared__ float ks[T_ * D_];
    __shared__ float vs[T_ * D_];
    for (int i = tid; i < T_ * D_; i += 128) {
        int t = i >> 6, d = i & 63;
        size_t off = ((size_t)(b * T_) + t) * HD_ + h * D_ + d;
        ks[i] = k2[off];
        vs[i] = v2[off];
    }
    __syncthreads();

    float qreg[D_];
    const float* qp = q + ((size_t)(b * S_) + s) * HD_ + h * D_;
#pragma unroll
    for (int d = 0; d < D_; d++) qreg[d] = qp[d];

    float m = -1e30f, ssum = 0.f;
    float cacc[D_];
#pragma unroll
    for (int d = 0; d < D_; d++) cacc[d] = 0.f;

    for (int t = 0; t < T_; t++) {
        const float* kp = &ks[t * D_];
        float l = 0.f;
#pragma unroll
        for (int d = 0; d < D_; d++) l += qreg[d] * kp[d];
        l *= SCALE_;
        float mn = fmaxf(m, l);
        float fs = expf(m - mn);
        float p  = expf(l - mn);
        ssum = ssum * fs + p;
        const float* vp = &vs[t * D_];
#pragma unroll
        for (int d = 0; d < D_; d++) cacc[d] = cacc[d] * fs + p * vp[d];
        m = mn;
    }
    float inv = 1.f / ssum;
    float* cp = ctx + ((size_t)(b * S_) + s) * HD_ + h * D_;
#pragma unroll
    for (int d = 0; d < D_; d++) cp[d] = cacc[d] * inv;
}

// ---------------- context batch-sum + patch injection ----------------
__global__ void ctx_sum_k(const float* __restrict__ ctx, float* __restrict__ csum)
{
    size_t i = (size_t)blockIdx.x * blockDim.x + threadIdx.x;
    if (i >= (size_t)S_ * HD_) return;
    float s = 0.f;
#pragma unroll
    for (int b = 0; b < B_; b++) s += ctx[(size_t)b * S_ * HD_ + i];
    csum[i] = s;
}

__global__ void inject_k(float* __restrict__ ctx, const float* __restrict__ csum,
                         const int* __restrict__ posmask)
{
    size_t i = (size_t)blockIdx.x * blockDim.x + threadIdx.x;
    if (i >= (size_t)B_ * S_ * HD_) return;
    size_t r = i % ((size_t)S_ * HD_);
    int b = (int)(i / ((size_t)S_ * HD_));
    int s = (int)(r / HD_);
    if (!posmask[b * S_ + s]) return;
    float x = ctx[i];
    float mo = (csum[r] - x) * (1.f / (float)(B_ - 1));
    ctx[i] = x + WINJ_ * (mo - x);
}

// ---------------- launch ----------------
extern "C" void kernel_launch(void* const* d_in, const int* in_sizes, int n_in,
                              void* d_out, int out_size)
{
    (void)in_sizes; (void)n_in; (void)out_size;
    const float* X  = (const float*)d_in[0];
    const float* E  = (const float*)d_in[1];
    const float* Wq = (const float*)d_in[2];
    const float* Wk = (const float*)d_in[3];
    const float* Wv = (const float*)d_in[4];
    const float* Wo = (const float*)d_in[5];
    const float* bo = (const float*)d_in[6];
    float* out = (float*)d_out;

    float *q, *k, *v, *k2, *v2, *probs, *tokpart, *tokscores, *posscores, *ctx, *csum;
    int *tokmask, *posmask;
    cudaGetSymbolAddress((void**)&q,        g_q);
    cudaGetSymbolAddress((void**)&k,        g_k);
    cudaGetSymbolAddress((void**)&v,        g_v);
    cudaGetSymbolAddress((void**)&k2,       g_k2);
    cudaGetSymbolAddress((void**)&v2,       g_v2);
    cudaGetSymbolAddress((void**)&probs,    g_probs);
    cudaGetSymbolAddress((void**)&tokpart,  g_tokpart);
    cudaGetSymbolAddress((void**)&tokscores,g_tokscores);
    cudaGetSymbolAddress((void**)&tokmask,  g_tokmask);
    cudaGetSymbolAddress((void**)&posscores,g_posscores);
    cudaGetSymbolAddress((void**)&posmask,  g_posmask);
    cudaGetSymbolAddress((void**)&ctx,      g_ctx);
    cudaGetSymbolAddress((void**)&csum,     g_ctxsum);

    // 1. projections
    sgemm_k<0><<<dim3(HD_ / 128, (B_ * S_) / 128), 256>>>(X, Wq, q, B_ * S_, HD_, C_, nullptr, nullptr);
    sgemm_k<0><<<dim3(HD_ / 128, (B_ * T_ + 127) / 128), 256>>>(E, Wk, k, B_ * T_, HD_, CE_, nullptr, nullptr);
    sgemm_k<0><<<dim3(HD_ / 128, (B_ * T_ + 127) / 128), 256>>>(E, Wv, v, B_ * T_, HD_, CE_, nullptr, nullptr);

    // 2. first attention pass -> probs + token partial sums
    attn1_k<<<dim3(SCHUNK_, H_, B_), 128>>>(q, k, probs, tokpart);
    tok_reduce_k<<<(B_ * T_ + 255) / 256, 256>>>(tokpart, tokscores);
    tok_topk_k<<<B_, 128>>>(tokscores, tokmask);

    // 3. position scores + top-k
    pos_scores_k<<<dim3(S_ / 256, B_), 256>>>(probs, tokmask, posscores);
    pos_topk_k<<<dim3(S_ / 256, B_), 256>>>(posscores, posmask);

    // 4. cross-frame K/V mixing
    kvmix_k<<<(T_ * HD_ + 255) / 256, 256>>>(k, v, tokmask, k2, v2);

    // 5. second attention pass -> context
    attn2_k<<<dim3(SCHUNK_, H_, B_), 128>>>(q, k2, v2, ctx);

    // 6. patch correspondence injection
    ctx_sum_k<<<(int)(((size_t)S_ * HD_ + 255) / 256), 256>>>(ctx, csum);
    inject_k<<<(int)(((size_t)B_ * S_ * HD_ + 255) / 256), 256>>>(ctx, csum, posmask);

    // 7. output projection + bias + residual
    sgemm_k<1><<<dim3(HD_ / 128, (B_ * S_) / 128), 256>>>(ctx, Wo, out, B_ * S_, HD_, C_, bo, X);
}

// round 2
// speedup vs baseline: 1.2081x; 1.2081x over previous
#include <cuda_runtime.h>
#include <math.h>
#include <stdint.h>

#define B_  8
#define S_  4096
#define T_  77
#define C_  1280
#define CE_ 2048
#define H_  20
#define D_  64
#define HD_ 1280
#define KTOK_ 12
#define KPOS_ 1229
#define SCHUNK_ (S_/128)   // 32

#define SCALE_ 0.125f
#define STRENGTH_ 0.5f
#define ALPHA_ 0.7f
#define WINJ_ 0.25f        // FIW * STRENGTH

// ---------------- scratch (device globals; no allocations) ----------------
__device__ float g_q[(size_t)B_*S_*HD_];
__device__ float g_k[B_*T_*HD_];
__device__ float g_v[B_*T_*HD_];
__device__ float g_k2[B_*T_*HD_];
__device__ float g_v2[B_*T_*HD_];
__device__ float g_probs[(size_t)B_*H_*S_*T_];
__device__ float g_tokpart[B_*H_*SCHUNK_*T_];
__device__ float g_tokscores[B_*T_];
__device__ int   g_tokmask[B_*T_];
__device__ float g_posscores[B_*S_];
__device__ int   g_posmask[B_*S_];
__device__ float g_ctx[(size_t)B_*S_*HD_];
__device__ float g_ctxsum[(size_t)S_*HD_];

// ---------------- tf32 helpers ----------------
__device__ __forceinline__ uint32_t f2tf32(float x) {
    uint32_t u;
    asm("cvt.rna.tf32.f32 %0, %1;" : "=r"(u) : "f"(x));
    return u;
}

__device__ __forceinline__ void mma_tf32(float* c, const uint32_t* a, const uint32_t* b) {
    asm volatile(
        "mma.sync.aligned.m16n8k8.row.col.f32.tf32.tf32.f32 "
        "{%0,%1,%2,%3},{%4,%5,%6,%7},{%8,%9},{%0,%1,%2,%3};"
        : "+f"(c[0]), "+f"(c[1]), "+f"(c[2]), "+f"(c[3])
        : "r"(a[0]), "r"(a[1]), "r"(a[2]), "r"(a[3]), "r"(b[0]), "r"(b[1]));
}

// ---------------- tf32 tensor-core GEMM: 128x128x16 tiles, 256 threads ----------------
// warp layout 2x4, each warp computes 64x32 via 4x4 m16n8k8 mma tiles
template<int EPI>
__global__ __launch_bounds__(256) void tf32gemm_k(
    const float* __restrict__ A, const float* __restrict__ Bm, float* __restrict__ Cm,
    int M, int N, int K,
    const float* __restrict__ bias, const float* __restrict__ resid)
{
    __shared__ float As[16][132];   // [k][m], k-major for fragment gather
    __shared__ float Bs[16][132];   // [k][n]

    const int tid  = threadIdx.x;
    const int wid  = tid >> 5, lane = tid & 31;
    const int wm   = wid & 1;        // 0..1 : 64-row slab
    const int wn   = wid >> 1;       // 0..3 : 32-col slab
    const int bm0  = blockIdx.y * 128;
    const int bn0  = blockIdx.x * 128;

    float acc[4][4][4];
#pragma unroll
    for (int i = 0; i < 4; i++)
#pragma unroll
        for (int j = 0; j < 4; j++)
#pragma unroll
            for (int r = 0; r < 4; r++) acc[i][j][r] = 0.f;

    // gmem load mapping (2 float4 per thread per matrix per tile)
    // A: idx 0..511 : row = idx>>2 (0..127), c4 = idx&3
    // B: idx 0..511 : krow = idx>>5 (0..15), col4 = idx&31
    float4 pa[2], pb[2];

    const int aIdx0 = tid * 2;
#pragma unroll
    for (int i = 0; i < 2; i++) {
        int idx = aIdx0 + i;
        int r = bm0 + (idx >> 2);
        int c4 = (idx & 3) * 4;
        pa[i] = (r < M) ? *(const float4*)(A + (size_t)r * K + c4)
                        : make_float4(0.f, 0.f, 0.f, 0.f);
        int kr = idx >> 5;
        int n4 = (idx & 31) * 4;
        pb[i] = *(const float4*)(Bm + (size_t)kr * N + bn0 + n4);
    }

    for (int k0 = 0; k0 < K; k0 += 16) {
        // store staged regs into smem (A transposed to k-major) with tf32 rounding
#pragma unroll
        for (int i = 0; i < 2; i++) {
            int idx = aIdx0 + i;
            int r = idx >> 2;
            int c4 = (idx & 3) * 4;
            As[c4 + 0][r] = __uint_as_float(f2tf32(pa[i].x));
            As[c4 + 1][r] = __uint_as_float(f2tf32(pa[i].y));
            As[c4 + 2][r] = __uint_as_float(f2tf32(pa[i].z));
            As[c4 + 3][r] = __uint_as_float(f2tf32(pa[i].w));
            int kr = idx >> 5;
            int n4 = (idx & 31) * 4;
            float4 bb;
            bb.x = __uint_as_float(f2tf32(pb[i].x));
            bb.y = __uint_as_float(f2tf32(pb[i].y));
            bb.z = __uint_as_float(f2tf32(pb[i].z));
            bb.w = __uint_as_float(f2tf32(pb[i].w));
            *(float4*)&Bs[kr][n4] = bb;
        }
        __syncthreads();

        // prefetch next tile while computing this one
        if (k0 + 16 < K) {
#pragma unroll
            for (int i = 0; i < 2; i++) {
                int idx = aIdx0 + i;
                int r = bm0 + (idx >> 2);
                int c4 = (idx & 3) * 4;
                pa[i] = (r < M) ? *(const float4*)(A + (size_t)r * K + k0 + 16 + c4)
                                : make_float4(0.f, 0.f, 0.f, 0.f);
                int kr = idx >> 5;
                int n4 = (idx & 31) * 4;
                pb[i] = *(const float4*)(Bm + (size_t)(k0 + 16 + kr) * N + bn0 + n4);
            }
        }

#pragma unroll
        for (int kk = 0; kk < 16; kk += 8) {
            const int kb = kk + (lane & 3);
            const int ra = wm * 64 + (lane >> 2);
            const int cb = wn * 32 + (lane >> 2);
            uint32_t af[4][4], bf[4][2];
#pragma unroll
            for (int mt = 0; mt < 4; mt++) {
                int r = ra + mt * 16;
                af[mt][0] = __float_as_uint(As[kb][r]);
                af[mt][1] = __float_as_uint(As[kb][r + 8]);
                af[mt][2] = __float_as_uint(As[kb + 4][r]);
                af[mt][3] = __float_as_uint(As[kb + 4][r + 8]);
            }
#pragma unroll
            for (int nt = 0; nt < 4; nt++) {
                bf[nt][0] = __float_as_uint(Bs[kb][cb + nt * 8]);
                bf[nt][1] = __float_as_uint(Bs[kb + 4][cb + nt * 8]);
            }
#pragma unroll
            for (int mt = 0; mt < 4; mt++)
#pragma unroll
                for (int nt = 0; nt < 4; nt++)
                    mma_tf32(acc[mt][nt], af[mt], bf[nt]);
        }
        __syncthreads();
    }

    // epilogue: c0,c1 -> (row, col..col+1); c2,c3 -> (row+8, col..col+1)
    const int row0 = bm0 + wm * 64 + (lane >> 2);
    const int col0 = bn0 + wn * 32 + 2 * (lane & 3);
#pragma unroll
    for (int mt = 0; mt < 4; mt++) {
#pragma unroll
        for (int nt = 0; nt < 4; nt++) {
            int r = row0 + mt * 16;
            int c = col0 + nt * 8;
            float v0 = acc[mt][nt][0], v1 = acc[mt][nt][1];
            float v2 = acc[mt][nt][2], v3 = acc[mt][nt][3];
            if (EPI) {
                float b0v = bias[c], b1v = bias[c + 1];
                if (r < M) {
                    float2 rr = *(const float2*)(resid + (size_t)r * N + c);
                    v0 += b0v + rr.x; v1 += b1v + rr.y;
                }
                if (r + 8 < M) {
                    float2 rr = *(const float2*)(resid + (size_t)(r + 8) * N + c);
                    v2 += b0v + rr.x; v3 += b1v + rr.y;
                }
            }
            if (r < M) { float2 o; o.x = v0; o.y = v1; *(float2*)(Cm + (size_t)r * N + c) = o; }
            if (r + 8 < M) { float2 o; o.x = v2; o.y = v3; *(float2*)(Cm + (size_t)(r + 8) * N + c) = o; }
        }
    }
}

// ---------------- attention pass 1 ----------------
// no online max (logits bounded ~|4|). pass A: e=exp(l), accumulate sum, store e.
// pass B: normalize from L2-hot re-read, accumulate token partials.
__global__ __launch_bounds__(128) void attn1_k(
    const float* __restrict__ q, const float* __restrict__ kk,
    float* __restrict__ probs, float* __restrict__ tokpart)
{
    const int b = blockIdx.z, h = blockIdx.y;
    const int tid = threadIdx.x;
    const int s = blockIdx.x * 128 + tid;
    __shared__ float ks[T_ * D_];
    __shared__ float tpw[4][T_];
    const int w = tid >> 5, lane = tid & 31;

    for (int i = tid; i < T_ * (D_ / 4); i += 128) {
        int t = i >> 4, d4 = (i & 15);
        *(float4*)&ks[t * D_ + d4 * 4] =
            *(const float4*)&kk[((size_t)(b * T_ + t)) * HD_ + h * D_ + d4 * 4];
    }
    for (int i = lane; i < T_; i += 32) tpw[w][i] = 0.f;
    __syncthreads();

    float qreg[D_];
    const float* qp = q + ((size_t)(b * S_) + s) * HD_ + h * D_;
#pragma unroll
    for (int d = 0; d < D_; d++) qreg[d] = qp[d];

    const size_t pbase = (((size_t)(b * H_) + h) * S_ + s) * T_;
    float ssum = 0.f;
    for (int t = 0; t < T_; t++) {
        const float* kp = &ks[t * D_];
        float l = 0.f;
#pragma unroll
        for (int d = 0; d < D_; d++) l += qreg[d] * kp[d];
        float e = __expf(l * SCALE_);
        ssum += e;
        probs[pbase + t] = e;
    }
    const float inv = 1.f / ssum;
    for (int t = 0; t < T_; t++) {
        float p = probs[pbase + t] * inv;
        probs[pbase + t] = p;
#pragma unroll
        for (int o = 16; o; o >>= 1) p += __shfl_xor_sync(0xffffffffu, p, o);
        if (lane == 0) tpw[w][t] += p;
    }
    __syncthreads();
    if (tid < T_) {
        int lin = (b * H_ + h) * SCHUNK_ + blockIdx.x;
        tokpart[(size_t)lin * T_ + tid] = tpw[0][tid] + tpw[1][tid] + tpw[2][tid] + tpw[3][tid];
    }
}

// ---------------- token score reduce + top-k ----------------
__global__ void tok_reduce_k(const float* __restrict__ tokpart, float* __restrict__ scores)
{
    int idx = blockIdx.x * blockDim.x + threadIdx.x;
    if (idx >= B_ * T_) return;
    int b = idx / T_, t = idx % T_;
    float sum = 0.f;
    for (int h = 0; h < H_; h++)
        for (int c = 0; c < SCHUNK_; c++)
            sum += tokpart[(size_t)((b * H_ + h) * SCHUNK_ + c) * T_ + t];
    scores[idx] = sum * (1.f / (float)(H_ * S_));
}

__global__ void tok_topk_k(const float* __restrict__ scores, int* __restrict__ mask)
{
    int b = blockIdx.x, tid = threadIdx.x;
    __shared__ float sc[T_];
    if (tid < T_) sc[tid] = scores[b * T_ + tid];
    __syncthreads();
    if (tid < T_) {
        float v = sc[tid];
        int rank = 0;
        for (int j = 0; j < T_; j++) {
            float u = sc[j];
            rank += (int)((u > v) || (u == v && j < tid));
        }
        mask[b * T_ + tid] = (rank < KTOK_) ? 1 : 0;
    }
}

// ---------------- position scores + top-k ----------------
__global__ __launch_bounds__(256) void pos_scores_k(
    const float* __restrict__ probs, const int* __restrict__ tokmask, float* __restrict__ out)
{
    const int b = blockIdx.y;
    const int s = blockIdx.x * 256 + threadIdx.x;
    __shared__ float msk[T_];
    if (threadIdx.x < T_) msk[threadIdx.x] = (float)tokmask[b * T_ + threadIdx.x];
    __syncthreads();
    float sum = 0.f;
    for (int h = 0; h < H_; h++) {
        const float* p = probs + (((size_t)(b * H_) + h) * S_ + s) * T_;
        for (int t = 0; t < T_; t++) sum += p[t] * msk[t];
    }
    out[b * S_ + s] = sum * (1.f / (float)H_);
}

__global__ __launch_bounds__(256) void pos_topk_k(const float* __restrict__ scores, int* __restrict__ mask)
{
    const int b = blockIdx.y;
    __shared__ float sc[S_];
    for (int i = threadIdx.x; i < S_; i += 256) sc[i] = scores[b * S_ + i];
    __syncthreads();
    const int i = blockIdx.x * 256 + threadIdx.x;
    float v = sc[i];
    int rank = 0;
    for (int j = 0; j < S_; j++) {
        float u = sc[j];
        rank += (int)((u > v) || (u == v && j < i));
    }
    mask[b * S_ + i] = (rank < KPOS_) ? 1 : 0;
}

// ---------------- cross-frame K/V mixing ----------------
__global__ void kvmix_k(const float* __restrict__ kin, const float* __restrict__ vin,
                        const int* __restrict__ tokmask,
                        float* __restrict__ k2, float* __restrict__ v2)
{
    int idx = blockIdx.x * blockDim.x + threadIdx.x;
    if (idx >= T_ * HD_) return;
    int t = idx / HD_;
    int c = idx % HD_;
    float kv[B_], vv[B_];
    float ksum = 0.f, vsum = 0.f;
#pragma unroll
    for (int b = 0; b < B_; b++) {
        size_t off = ((size_t)(b * T_) + t) * HD_ + c;
        kv[b] = kin[off];
        vv[b] = vin[off];
        ksum += kv[b];
        vsum += vv[b];
    }
#pragma unroll
    for (int b = 0; b < B_; b++) {
        float tm = tokmask[b * T_ + t] ? STRENGTH_ : 0.f;
        size_t off = ((size_t)(b * T_) + t) * HD_ + c;
        float x  = kv[b];
        float mo = (ksum - x) * (1.f / (float)(B_ - 1));
        float mixed = ALPHA_ * x + (1.f - ALPHA_) * mo;
        k2[off] = x + tm * (mixed - x);
        x  = vv[b];
        mo = (vsum - x) * (1.f / (float)(B_ - 1));
        mixed = ALPHA_ * x + (1.f - ALPHA_) * mo;
        v2[off] = x + tm * (mixed - x);
    }
}

// ---------------- attention pass 2 ----------------
__global__ __launch_bounds__(128) void attn2_k(
    const float* __restrict__ q, const float* __restrict__ k2,
    const float* __restrict__ v2, float* __restrict__ ctx)
{
    const int b = blockIdx.z, h = blockIdx.y;
    const int tid = threadIdx.x;
    const int s = blockIdx.x * 128 + tid;
    __shared__ float ks[T_ * D_];
    __shared__ float vs[T_ * D_];
    for (int i = tid; i < T_ * (D_ / 4); i += 128) {
        int t = i >> 4, d4 = (i & 15);
        size_t off = ((size_t)(b * T_) + t) * HD_ + h * D_ + d4 * 4;
        *(float4*)&ks[t * D_ + d4 * 4] = *(const float4*)&k2[off];
        *(float4*)&vs[t * D_ + d4 * 4] = *(const float4*)&v2[off];
    }
    __syncthreads();

    float qreg[D_];
    const float* qp = q + ((size_t)(b * S_) + s) * HD_ + h * D_;
#pragma unroll
    for (int d = 0; d < D_; d++) qreg[d] = qp[d];

    float ssum = 0.f;
    float cacc[D_];
#pragma unroll
    for (int d = 0; d < D_; d++) cacc[d] = 0.f;

    for (int t = 0; t < T_; t++) {
        const float* kp = &ks[t * D_];
        float l = 0.f;
#pragma unroll
        for (int d = 0; d < D_; d++) l += qreg[d] * kp[d];
        float e = __expf(l * SCALE_);
        ssum += e;
        const float* vp = &vs[t * D_];
#pragma unroll
        for (int d = 0; d < D_; d++) cacc[d] += e * vp[d];
    }
    float inv = 1.f / ssum;
    float* cp = ctx + ((size_t)(b * S_) + s) * HD_ + h * D_;
#pragma unroll
    for (int d = 0; d < D_; d++) cp[d] = cacc[d] * inv;
}

// ---------------- context batch-sum + patch injection ----------------
__global__ void ctx_sum_k(const float* __restrict__ ctx, float* __restrict__ csum)
{
    size_t i = (size_t)blockIdx.x * blockDim.x + threadIdx.x;
    if (i >= (size_t)S_ * HD_) return;
    float s = 0.f;
#pragma unroll
    for (int b = 0; b < B_; b++) s += ctx[(size_t)b * S_ * HD_ + i];
    csum[i] = s;
}

__global__ void inject_k(float* __restrict__ ctx, const float* __restrict__ csum,
                         const int* __restrict__ posmask)
{
    size_t i = (size_t)blockIdx.x * blockDim.x + threadIdx.x;
    if (i >= (size_t)B_ * S_ * HD_) return;
    size_t r = i % ((size_t)S_ * HD_);
    int b = (int)(i / ((size_t)S_ * HD_));
    int s = (int)(r / HD_);
    if (!posmask[b * S_ + s]) return;
    float x = ctx[i];
    float mo = (csum[r] - x) * (1.f / (float)(B_ - 1));
    ctx[i] = x + WINJ_ * (mo - x);
}

// ---------------- launch ----------------
extern "C" void kernel_launch(void* const* d_in, const int* in_sizes, int n_in,
                              void* d_out, int out_size)
{
    (void)in_sizes; (void)n_in; (void)out_size;
    const float* X  = (const float*)d_in[0];
    const float* E  = (const float*)d_in[1];
    const float* Wq = (const float*)d_in[2];
    const float* Wk = (const float*)d_in[3];
    const float* Wv = (const float*)d_in[4];
    const float* Wo = (const float*)d_in[5];
    const float* bo = (const float*)d_in[6];
    float* out = (float*)d_out;

    float *q, *k, *v, *k2, *v2, *probs, *tokpart, *tokscores, *posscores, *ctx, *csum;
    int *tokmask, *posmask;
    cudaGetSymbolAddress((void**)&q,        g_q);
    cudaGetSymbolAddress((void**)&k,        g_k);
    cudaGetSymbolAddress((void**)&v,        g_v);
    cudaGetSymbolAddress((void**)&k2,       g_k2);
    cudaGetSymbolAddress((void**)&v2,       g_v2);
    cudaGetSymbolAddress((void**)&probs,    g_probs);
    cudaGetSymbolAddress((void**)&tokpart,  g_tokpart);
    cudaGetSymbolAddress((void**)&tokscores,g_tokscores);
    cudaGetSymbolAddress((void**)&tokmask,  g_tokmask);
    cudaGetSymbolAddress((void**)&posscores,g_posscores);
    cudaGetSymbolAddress((void**)&posmask,  g_posmask);
    cudaGetSymbolAddress((void**)&ctx,      g_ctx);
    cudaGetSymbolAddress((void**)&csum,     g_ctxsum);

    // 1. projections (tensor-core tf32)
    tf32gemm_k<0><<<dim3(HD_ / 128, (B_ * S_) / 128), 256>>>(X, Wq, q, B_ * S_, HD_, C_, nullptr, nullptr);
    tf32gemm_k<0><<<dim3(HD_ / 128, (B_ * T_ + 127) / 128), 256>>>(E, Wk, k, B_ * T_, HD_, CE_, nullptr, nullptr);
    tf32gemm_k<0><<<dim3(HD_ / 128, (B_ * T_ + 127) / 128), 256>>>(E, Wv, v, B_ * T_, HD_, CE_, nullptr, nullptr);

    // 2. first attention pass -> probs + token partial sums
    attn1_k<<<dim3(SCHUNK_, H_, B_), 128>>>(q, k, probs, tokpart);
    tok_reduce_k<<<(B_ * T_ + 255) / 256, 256>>>(tokpart, tokscores);
    tok_topk_k<<<B_, 128>>>(tokscores, tokmask);

    // 3. position scores + top-k
    pos_scores_k<<<dim3(S_ / 256, B_), 256>>>(probs, tokmask, posscores);
    pos_topk_k<<<dim3(S_ / 256, B_), 256>>>(posscores, posmask);

    // 4. cross-frame K/V mixing
    kvmix_k<<<(T_ * HD_ + 255) / 256, 256>>>(k, v, tokmask, k2, v2);

    // 5. second attention pass -> context
    attn2_k<<<dim3(SCHUNK_, H_, B_), 128>>>(q, k2, v2, ctx);

    // 6. patch correspondence injection
    ctx_sum_k<<<(int)(((size_t)S_ * HD_ + 255) / 256), 256>>>(ctx, csum);
    inject_k<<<(int)(((size_t)B_ * S_ * HD_ + 255) / 256), 256>>>(ctx, csum, posmask);

    // 7. output projection + bias + residual (tensor-core tf32)
    tf32gemm_k<1><<<dim3(HD_ / 128, (B_ * S_) / 128), 256>>>(ctx, Wo, out, B_ * S_, HD_, C_, bo, X);
}

// round 5
// speedup vs baseline: 1.8447x; 1.5269x over previous
#include <cuda_runtime.h>
#include <cuda_fp16.h>
#include <math.h>
#include <stdint.h>

#define B_  8
#define S_  4096
#define T_  77
#define C_  1280
#define CE_ 2048
#define H_  20
#define D_  64
#define HD_ 1280
#define KTOK_ 12
#define KPOS_ 1229
#define SCHUNK_ (S_/128)   // 32

#define SCALE_ 0.125f
#define STRENGTH_ 0.5f
#define ALPHA_ 0.7f
#define WINJ_ 0.25f        // FIW * STRENGTH

// ---------------- scratch (device globals; no allocations) ----------------
__device__ float g_q[(size_t)B_*S_*HD_];
__device__ float g_k[B_*T_*HD_];
__device__ float g_v[B_*T_*HD_];
__device__ float g_k2[B_*T_*HD_];
__device__ float g_v2[B_*T_*HD_];
__device__ float g_probs[(size_t)B_*H_*S_*T_];    // unnormalized e
__device__ float g_rowinv[B_*H_*S_];
__device__ float g_tokpart[B_*H_*SCHUNK_*T_];
__device__ float g_tokscores[B_*T_];
__device__ int   g_tokmask[B_*T_];
__device__ float g_posscores[B_*S_];
__device__ int   g_posmask[B_*S_];
__device__ float g_ctx[(size_t)B_*S_*HD_];
__device__ float g_ctxsum[(size_t)S_*HD_];

// ====================================================================
//  fp16 mma.sync GEMM : 128x128x32 tiles, 256 threads, warp tile 64x32
// ====================================================================
#define KP_ 40   // smem k-pitch in halves (32 data + 8 pad)

__device__ __forceinline__ void mma_f16(float* c, const uint32_t* a, const uint32_t* b) {
    asm volatile(
        "mma.sync.aligned.m16n8k16.row.col.f32.f16.f16.f32 "
        "{%0,%1,%2,%3},{%4,%5,%6,%7},{%8,%9},{%0,%1,%2,%3};"
        : "+f"(c[0]), "+f"(c[1]), "+f"(c[2]), "+f"(c[3])
        : "r"(a[0]), "r"(a[1]), "r"(a[2]), "r"(a[3]), "r"(b[0]), "r"(b[1]));
}

__device__ __forceinline__ uint32_t pack_h2(float x, float y) {
    __half2 h = __floats2half2_rn(x, y);
    return *(uint32_t*)&h;
}

template<int EPI>
__global__ __launch_bounds__(256) void h16gemm_k(
    const float* __restrict__ A, const float* __restrict__ Bm, float* __restrict__ Cm,
    int M, int N, int K,
    const float* __restrict__ bias, const float* __restrict__ resid)
{
    __shared__ __half As[128][KP_];
    __shared__ __half Bs[128][KP_];

    const int tid  = threadIdx.x;
    const int wid  = tid >> 5, lane = tid & 31;
    const int wm   = wid & 1;
    const int wn   = wid >> 1;
    const int bm0  = blockIdx.y * 128;
    const int bn0  = blockIdx.x * 128;

    float acc[4][4][4];
#pragma unroll
    for (int i = 0; i < 4; i++)
#pragma unroll
        for (int j = 0; j < 4; j++)
#pragma unroll
            for (int r = 0; r < 4; r++) acc[i][j][r] = 0.f;

    // staging regs: 4 float4 each for A and B per 32-k tile
    float4 pa[4], pb[4];
#pragma unroll
    for (int i = 0; i < 4; i++) {
        int f = tid + i * 256;
        int row = f >> 3;
        int kc4 = (f & 7) * 4;
        int r = bm0 + row;
        pa[i] = (r < M) ? *(const float4*)(A + (size_t)r * K + kc4)
                        : make_float4(0.f, 0.f, 0.f, 0.f);
        int kr = f >> 5;
        int n4 = (f & 31) * 4;
        pb[i] = *(const float4*)(Bm + (size_t)kr * N + bn0 + n4);
    }

    for (int k0 = 0; k0 < K; k0 += 32) {
        // write staged regs to smem as half
#pragma unroll
        for (int i = 0; i < 4; i++) {
            int f = tid + i * 256;
            int row = f >> 3;
            int kc4 = (f & 7) * 4;
            uint32_t* dst = (uint32_t*)&As[row][kc4];
            dst[0] = pack_h2(pa[i].x, pa[i].y);
            dst[1] = pack_h2(pa[i].z, pa[i].w);
            int kr = f >> 5;
            int n4 = (f & 31) * 4;
            Bs[n4 + 0][kr] = __float2half_rn(pb[i].x);
            Bs[n4 + 1][kr] = __float2half_rn(pb[i].y);
            Bs[n4 + 2][kr] = __float2half_rn(pb[i].z);
            Bs[n4 + 3][kr] = __float2half_rn(pb[i].w);
        }
        __syncthreads();

        // prefetch next tile
        if (k0 + 32 < K) {
#pragma unroll
            for (int i = 0; i < 4; i++) {
                int f = tid + i * 256;
                int row = f >> 3;
                int kc4 = (f & 7) * 4;
                int r = bm0 + row;
                pa[i] = (r < M) ? *(const float4*)(A + (size_t)r * K + k0 + 32 + kc4)
                                : make_float4(0.f, 0.f, 0.f, 0.f);
                int kr = f >> 5;
                int n4 = (f & 31) * 4;
                pb[i] = *(const float4*)(Bm + (size_t)(k0 + 32 + kr) * N + bn0 + n4);
            }
        }

#pragma unroll
        for (int kk = 0; kk < 32; kk += 16) {
            const int kf = kk + (lane & 3) * 2;   // half index within row
            const int mr = wm * 64 + (lane >> 2);
            const int nr = wn * 32 + (lane >> 2);
            uint32_t af[4][4], bf[4][2];
#pragma unroll
            for (int mt = 0; mt < 4; mt++) {
                int m = mr + mt * 16;
                af[mt][0] = *(const uint32_t*)&As[m][kf];
                af[mt][1] = *(const uint32_t*)&As[m + 8][kf];
                af[mt][2] = *(const uint32_t*)&As[m][kf + 8];
                af[mt][3] = *(const uint32_t*)&As[m + 8][kf + 8];
            }
#pragma unroll
            for (int nt = 0; nt < 4; nt++) {
                int n = nr + nt * 8;
                bf[nt][0] = *(const uint32_t*)&Bs[n][kf];
                bf[nt][1] = *(const uint32_t*)&Bs[n][kf + 8];
            }
#pragma unroll
            for (int mt = 0; mt < 4; mt++)
#pragma unroll
                for (int nt = 0; nt < 4; nt++)
                    mma_f16(acc[mt][nt], af[mt], bf[nt]);
        }
        __syncthreads();
    }

    const int row0 = bm0 + wm * 64 + (lane >> 2);
    const int col0 = bn0 + wn * 32 + 2 * (lane & 3);
#pragma unroll
    for (int mt = 0; mt < 4; mt++) {
#pragma unroll
        for (int nt = 0; nt < 4; nt++) {
            int r = row0 + mt * 16;
            int c = col0 + nt * 8;
            float v0 = acc[mt][nt][0], v1 = acc[mt][nt][1];
            float v2 = acc[mt][nt][2], v3 = acc[mt][nt][3];
            if (EPI) {
                float b0v = bias[c], b1v = bias[c + 1];
                if (r < M) {
                    float2 rr = *(const float2*)(resid + (size_t)r * N + c);
                    v0 += b0v + rr.x; v1 += b1v + rr.y;
                }
                if (r + 8 < M) {
                    float2 rr = *(const float2*)(resid + (size_t)(r + 8) * N + c);
                    v2 += b0v + rr.x; v3 += b1v + rr.y;
                }
            }
            if (r < M) { float2 o; o.x = v0; o.y = v1; *(float2*)(Cm + (size_t)r * N + c) = o; }
            if (r + 8 < M) { float2 o; o.x = v2; o.y = v3; *(float2*)(Cm + (size_t)(r + 8) * N + c) = o; }
        }
    }
}

// ---------------- attention pass 1 ----------------
__global__ __launch_bounds__(128) void attn1_k(
    const float* __restrict__ q, const float* __restrict__ kk,
    float* __restrict__ probs, float* __restrict__ rowinv, float* __restrict__ tokpart)
{
    const int b = blockIdx.z, h = blockIdx.y;
    const int tid = threadIdx.x;
    const int s = blockIdx.x * 128 + tid;
    __shared__ float ks[T_ * D_];
    __shared__ float tpw[4][T_];
    const int w = tid >> 5, lane = tid & 31;

    for (int i = tid; i < T_ * (D_ / 4); i += 128) {
        int t = i >> 4, d4 = (i & 15);
        *(float4*)&ks[t * D_ + d4 * 4] =
            *(const float4*)&kk[((size_t)(b * T_ + t)) * HD_ + h * D_ + d4 * 4];
    }
    for (int i = lane; i < T_; i += 32) tpw[w][i] = 0.f;
    __syncthreads();

    float4 q4[16];
    const float4* qp = (const float4*)(q + ((size_t)(b * S_) + s) * HD_ + h * D_);
#pragma unroll
    for (int j = 0; j < 16; j++) q4[j] = qp[j];

    const size_t pbase = (((size_t)(b * H_) + h) * S_ + s) * T_;
    float ssum = 0.f;
    for (int t = 0; t < T_; t++) {
        const float4* kp = (const float4*)&ks[t * D_];
        float l0 = 0.f, l1 = 0.f, l2 = 0.f, l3 = 0.f;
#pragma unroll
        for (int j = 0; j < 16; j++) {
            float4 kv = kp[j];
            l0 += q4[j].x * kv.x;
            l1 += q4[j].y * kv.y;
            l2 += q4[j].z * kv.z;
            l3 += q4[j].w * kv.w;
        }
        float e = __expf(((l0 + l1) + (l2 + l3)) * SCALE_);
        ssum += e;
        probs[pbase + t] = e;
    }
    const float inv = 1.f / ssum;
    rowinv[(size_t)(b * H_ + h) * S_ + s] = inv;
    for (int t = 0; t < T_; t++) {
        float p = probs[pbase + t] * inv;
#pragma unroll
        for (int o = 16; o; o >>= 1) p += __shfl_xor_sync(0xffffffffu, p, o);
        if (lane == 0) tpw[w][t] += p;
    }
    __syncthreads();
    if (tid < T_) {
        int lin = (b * H_ + h) * SCHUNK_ + blockIdx.x;
        tokpart[(size_t)lin * T_ + tid] = tpw[0][tid] + tpw[1][tid] + tpw[2][tid] + tpw[3][tid];
    }
}

// ---------------- token score reduce + top-k ----------------
__global__ void tok_reduce_k(const float* __restrict__ tokpart, float* __restrict__ scores)
{
    int idx = blockIdx.x * blockDim.x + threadIdx.x;
    if (idx >= B_ * T_) return;
    int b = idx / T_, t = idx % T_;
    float sum = 0.f;
    for (int h = 0; h < H_; h++)
        for (int c = 0; c < SCHUNK_; c++)
            sum += tokpart[(size_t)((b * H_ + h) * SCHUNK_ + c) * T_ + t];
    scores[idx] = sum * (1.f / (float)(H_ * S_));
}

__global__ void tok_topk_k(const float* __restrict__ scores, int* __restrict__ mask)
{
    int b = blockIdx.x, tid = threadIdx.x;
    __shared__ float sc[T_];
    if (tid < T_) sc[tid] = scores[b * T_ + tid];
    __syncthreads();
    if (tid < T_) {
        float v = sc[tid];
        int rank = 0;
        for (int j = 0; j < T_; j++) {
            float u = sc[j];
            rank += (int)((u > v) || (u == v && j < tid));
        }
        mask[b * T_ + tid] = (rank < KTOK_) ? 1 : 0;
    }
}

// ---------------- position scores + top-k ----------------
__global__ __launch_bounds__(256) void pos_scores_k(
    const float* __restrict__ probs, const float* __restrict__ rowinv,
    const int* __restrict__ tokmask, float* __restrict__ out)
{
    const int b = blockIdx.y;
    const int s = blockIdx.x * 256 + threadIdx.x;
    __shared__ float msk[T_];
    if (threadIdx.x < T_) msk[threadIdx.x] = (float)tokmask[b * T_ + threadIdx.x];
    __syncthreads();
    float sum = 0.f;
    for (int h = 0; h < H_; h++) {
        const float* p = probs + (((size_t)(b * H_) + h) * S_ + s) * T_;
        float part = 0.f;
        for (int t = 0; t < T_; t++) part += p[t] * msk[t];
        sum += part * rowinv[(size_t)(b * H_ + h) * S_ + s];
    }
    out[b * S_ + s] = sum * (1.f / (float)H_);
}

__global__ __launch_bounds__(256) void pos_topk_k(const float* __restrict__ scores, int* __restrict__ mask)
{
    const int b = blockIdx.y;
    __shared__ float sc[S_];
    for (int i = threadIdx.x; i < S_; i += 256) sc[i] = scores[b * S_ + i];
    __syncthreads();
    const int i = blockIdx.x * 256 + threadIdx.x;
    float v = sc[i];
    int rank = 0;
    for (int j = 0; j < S_; j++) {
        float u = sc[j];
        rank += (int)((u > v) || (u == v && j < i));
    }
    mask[b * S_ + i] = (rank < KPOS_) ? 1 : 0;
}

// ---------------- cross-frame K/V mixing ----------------
__global__ void kvmix_k(const float* __restrict__ kin, const float* __restrict__ vin,
                        const int* __restrict__ tokmask,
                        float* __restrict__ k2, float* __restrict__ v2)
{
    int idx = blockIdx.x * blockDim.x + threadIdx.x;
    if (idx >= T_ * HD_) return;
    int t = idx / HD_;
    int c = idx % HD_;
    float kv[B_], vv[B_];
    float ksum = 0.f, vsum = 0.f;
#pragma unroll
    for (int b = 0; b < B_; b++) {
        size_t off = ((size_t)(b * T_) + t) * HD_ + c;
        kv[b] = kin[off];
        vv[b] = vin[off];
        ksum += kv[b];
        vsum += vv[b];
    }
#pragma unroll
    for (int b = 0; b < B_; b++) {
        float tm = tokmask[b * T_ + t] ? STRENGTH_ : 0.f;
        size_t off = ((size_t)(b * T_) + t) * HD_ + c;
        float x  = kv[b];
        float mo = (ksum - x) * (1.f / (float)(B_ - 1));
        float mixed = ALPHA_ * x + (1.f - ALPHA_) * mo;
        k2[off] = x + tm * (mixed - x);
        x  = vv[b];
        mo = (vsum - x) * (1.f / (float)(B_ - 1));
        mixed = ALPHA_ * x + (1.f - ALPHA_) * mo;
        v2[off] = x + tm * (mixed - x);
    }
}

// ---------------- attention pass 2 ----------------
__global__ __launch_bounds__(128) void attn2_k(
    const float* __restrict__ q, const float* __restrict__ k2,
    const float* __restrict__ v2, float* __restrict__ ctx)
{
    const int b = blockIdx.z, h = blockIdx.y;
    const int tid = threadIdx.x;
    const int s = blockIdx.x * 128 + tid;
    __shared__ float ks[T_ * D_];
    __shared__ float vs[T_ * D_];
    for (int i = tid; i < T_ * (D_ / 4); i += 128) {
        int t = i >> 4, d4 = (i & 15);
        size_t off = ((size_t)(b * T_) + t) * HD_ + h * D_ + d4 * 4;
        *(float4*)&ks[t * D_ + d4 * 4] = *(const float4*)&k2[off];
        *(float4*)&vs[t * D_ + d4 * 4] = *(const float4*)&v2[off];
    }
    __syncthreads();

    float4 q4[16];
    const float4* qp = (const float4*)(q + ((size_t)(b * S_) + s) * HD_ + h * D_);
#pragma unroll
    for (int j = 0; j < 16; j++) q4[j] = qp[j];

    float ssum = 0.f;
    float4 cacc[16];
#pragma unroll
    for (int j = 0; j < 16; j++) cacc[j] = make_float4(0.f, 0.f, 0.f, 0.f);

    for (int t = 0; t < T_; t++) {
        const float4* kp = (const float4*)&ks[t * D_];
        float l0 = 0.f, l1 = 0.f, l2 = 0.f, l3 = 0.f;
#pragma unroll
        for (int j = 0; j < 16; j++) {
            float4 kv = kp[j];
            l0 += q4[j].x * kv.x;
            l1 += q4[j].y * kv.y;
            l2 += q4[j].z * kv.z;
            l3 += q4[j].w * kv.w;
        }
        float e = __expf(((l0 + l1) + (l2 + l3)) * SCALE_);
        ssum += e;
        const float4* vp = (const float4*)&vs[t * D_];
#pragma unroll
        for (int j = 0; j < 16; j++) {
            float4 vv = vp[j];
            cacc[j].x += e * vv.x;
            cacc[j].y += e * vv.y;
            cacc[j].z += e * vv.z;
            cacc[j].w += e * vv.w;
        }
    }
    float inv = 1.f / ssum;
    float4* cp = (float4*)(ctx + ((size_t)(b * S_) + s) * HD_ + h * D_);
#pragma unroll
    for (int j = 0; j < 16; j++) {
        float4 o;
        o.x = cacc[j].x * inv; o.y = cacc[j].y * inv;
        o.z = cacc[j].z * inv; o.w = cacc[j].w * inv;
        cp[j] = o;
    }
}

// ---------------- context batch-sum + patch injection ----------------
__global__ void ctx_sum_k(const float* __restrict__ ctx, float* __restrict__ csum)
{
    size_t i = (size_t)blockIdx.x * blockDim.x + threadIdx.x;
    if (i >= (size_t)S_ * HD_) return;
    float s = 0.f;
#pragma unroll
    for (int b = 0; b < B_; b++) s += ctx[(size_t)b * S_ * HD_ + i];
    csum[i] = s;
}

__global__ void inject_k(float* __restrict__ ctx, const float* __restrict__ csum,
                         const int* __restrict__ posmask)
{
    size_t i = (size_t)blockIdx.x * blockDim.x + threadIdx.x;
    if (i >= (size_t)B_ * S_ * HD_) return;
    size_t r = i % ((size_t)S_ * HD_);
    int b = (int)(i / ((size_t)S_ * HD_));
    int s = (int)(r / HD_);
    if (!posmask[b * S_ + s]) return;
    float x = ctx[i];
    float mo = (csum[r] - x) * (1.f / (float)(B_ - 1));
    ctx[i] = x + WINJ_ * (mo - x);
}

// ---------------- launch ----------------
extern "C" void kernel_launch(void* const* d_in, const int* in_sizes, int n_in,
                              void* d_out, int out_size)
{
    (void)in_sizes; (void)n_in; (void)out_size;
    const float* X  = (const float*)d_in[0];
    const float* E  = (const float*)d_in[1];
    const float* Wq = (const float*)d_in[2];
    const float* Wk = (const float*)d_in[3];
    const float* Wv = (const float*)d_in[4];
    const float* Wo = (const float*)d_in[5];
    const float* bo = (const float*)d_in[6];
    float* out = (float*)d_out;

    float *q, *k, *v, *k2, *v2, *probs, *rowinv, *tokpart, *tokscores, *posscores, *ctx, *csum;
    int *tokmask, *posmask;
    cudaGetSymbolAddress((void**)&q,        g_q);
    cudaGetSymbolAddress((void**)&k,        g_k);
    cudaGetSymbolAddress((void**)&v,        g_v);
    cudaGetSymbolAddress((void**)&k2,       g_k2);
    cudaGetSymbolAddress((void**)&v2,       g_v2);
    cudaGetSymbolAddress((void**)&probs,    g_probs);
    cudaGetSymbolAddress((void**)&rowinv,   g_rowinv);
    cudaGetSymbolAddress((void**)&tokpart,  g_tokpart);
    cudaGetSymbolAddress((void**)&tokscores,g_tokscores);
    cudaGetSymbolAddress((void**)&tokmask,  g_tokmask);
    cudaGetSymbolAddress((void**)&posscores,g_posscores);
    cudaGetSymbolAddress((void**)&posmask,  g_posmask);
    cudaGetSymbolAddress((void**)&ctx,      g_ctx);
    cudaGetSymbolAddress((void**)&csum,     g_ctxsum);

    // 1. projections (fp16 tensor cores, fp32 accumulate)
    h16gemm_k<0><<<dim3(HD_ / 128, (B_ * S_) / 128), 256>>>(X, Wq, q, B_ * S_, HD_, C_, nullptr, nullptr);
    h16gemm_k<0><<<dim3(HD_ / 128, (B_ * T_ + 127) / 128), 256>>>(E, Wk, k, B_ * T_, HD_, CE_, nullptr, nullptr);
    h16gemm_k<0><<<dim3(HD_ / 128, (B_ * T_ + 127) / 128), 256>>>(E, Wv, v, B_ * T_, HD_, CE_, nullptr, nullptr);

    // 2. first attention pass -> e + inv + token partial sums
    attn1_k<<<dim3(SCHUNK_, H_, B_), 128>>>(q, k, probs, rowinv, tokpart);
    tok_reduce_k<<<(B_ * T_ + 255) / 256, 256>>>(tokpart, tokscores);
    tok_topk_k<<<B_, 128>>>(tokscores, tokmask);

    // 3. position scores + top-k
    pos_scores_k<<<dim3(S_ / 256, B_), 256>>>(probs, rowinv, tokmask, posscores);
    pos_topk_k<<<dim3(S_ / 256, B_), 256>>>(posscores, posmask);

    // 4. cross-frame K/V mixing
    kvmix_k<<<(T_ * HD_ + 255) / 256, 256>>>(k, v, tokmask, k2, v2);

    // 5. second attention pass -> context
    attn2_k<<<dim3(SCHUNK_, H_, B_), 128>>>(q, k2, v2, ctx);

    // 6. patch correspondence injection
    ctx_sum_k<<<(int)(((size_t)S_ * HD_ + 255) / 256), 256>>>(ctx, csum);
    inject_k<<<(int)(((size_t)B_ * S_ * HD_ + 255) / 256), 256>>>(ctx, csum, posmask);

    // 7. output projection + bias + residual
    h16gemm_k<1><<<dim3(HD_ / 128, (B_ * S_) / 128), 256>>>(ctx, Wo, out, B_ * S_, HD_, C_, bo, X);
}

// round 6
// speedup vs baseline: 3.7196x; 2.0164x over previous
#include <cuda_runtime.h>
#include <cuda_fp16.h>
#include <math.h>
#include <stdint.h>

#define B_  8
#define S_  4096
#define T_  77
#define C_  1280
#define CE_ 2048
#define H_  20
#define D_  64
#define HD_ 1280
#define KTOK_ 12
#define KPOS_ 1229
#define SCHUNK_ (S_/128)   // 32

#define SCALE_ 0.125f
#define STRENGTH_ 0.5f
#define ALPHA_ 0.7f
#define WINJ_ 0.25f        // FIW * STRENGTH

// ---------------- scratch (device globals; no allocations) ----------------
__device__ float g_q[(size_t)B_*S_*HD_];
__device__ float g_k[B_*T_*HD_];
__device__ float g_v[B_*T_*HD_];
__device__ float g_k2[B_*T_*HD_];
__device__ float g_v2[B_*T_*HD_];
__device__ float g_probs[(size_t)B_*H_*S_*T_];    // unnormalized e
__device__ float g_rowinv[B_*H_*S_];
__device__ float g_tokpart[B_*H_*SCHUNK_*T_];
__device__ float g_tokscores[B_*T_];
__device__ int   g_tokmask[B_*T_];
__device__ float g_posscores[B_*S_];
__device__ int   g_posmask[B_*S_];
__device__ float g_ctx[(size_t)B_*S_*HD_];

// ====================================================================
//  fp16 mma.sync GEMM : 128x128x32 tiles, 256 threads, warp tile 64x32
//  fragment loads via ldmatrix
// ====================================================================
#define AKP_ 40    // As k-pitch (halves): 32 data + 8 pad
#define BNP_ 136   // Bs n-pitch (halves): 128 data + 8 pad

__device__ __forceinline__ void mma_f16(float* c, const uint32_t* a, const uint32_t* b) {
    asm volatile(
        "mma.sync.aligned.m16n8k16.row.col.f32.f16.f16.f32 "
        "{%0,%1,%2,%3},{%4,%5,%6,%7},{%8,%9},{%0,%1,%2,%3};"
        : "+f"(c[0]), "+f"(c[1]), "+f"(c[2]), "+f"(c[3])
        : "r"(a[0]), "r"(a[1]), "r"(a[2]), "r"(a[3]), "r"(b[0]), "r"(b[1]));
}

__device__ __forceinline__ void ldmx4(uint32_t* r, const void* p) {
    uint32_t a = (uint32_t)__cvta_generic_to_shared(p);
    asm volatile("ldmatrix.sync.aligned.m8n8.x4.shared.b16 {%0,%1,%2,%3}, [%4];"
                 : "=r"(r[0]), "=r"(r[1]), "=r"(r[2]), "=r"(r[3]) : "r"(a));
}
__device__ __forceinline__ void ldmx4t(uint32_t* r, const void* p) {
    uint32_t a = (uint32_t)__cvta_generic_to_shared(p);
    asm volatile("ldmatrix.sync.aligned.m8n8.x4.trans.shared.b16 {%0,%1,%2,%3}, [%4];"
                 : "=r"(r[0]), "=r"(r[1]), "=r"(r[2]), "=r"(r[3]) : "r"(a));
}

__device__ __forceinline__ uint32_t pack_h2(float x, float y) {
    __half2 h = __floats2half2_rn(x, y);
    return *(uint32_t*)&h;
}

template<int EPI>
__global__ __launch_bounds__(256) void h16gemm_k(
    const float* __restrict__ A, const float* __restrict__ Bm, float* __restrict__ Cm,
    int M, int N, int K,
    const float* __restrict__ bias, const float* __restrict__ resid)
{
    __shared__ __half As[128][AKP_];    // [m][k]
    __shared__ __half Bs[32][BNP_];     // [k][n]

    const int tid  = threadIdx.x;
    const int wid  = tid >> 5, lane = tid & 31;
    const int wm   = wid & 1;
    const int wn   = wid >> 1;
    const int bm0  = blockIdx.y * 128;
    const int bn0  = blockIdx.x * 128;

    float acc[4][4][4];
#pragma unroll
    for (int i = 0; i < 4; i++)
#pragma unroll
        for (int j = 0; j < 4; j++)
#pragma unroll
            for (int r = 0; r < 4; r++) acc[i][j][r] = 0.f;

    // precompute ldmatrix lane addresses
    const int ltile = lane >> 3, lrit = lane & 7;
    // A: tile t -> (m + (t&1)*8 + rit, k + (t>>1)*8), per mt
    const int a_m  = wm * 64 + (ltile & 1) * 8 + lrit;
    const int a_kc = (ltile >> 1) * 8;
    // B trans: tile t -> (k + (t&1)*8 + rit, n + (t>>1)*8), per pair p
    const int b_k  = (ltile & 1) * 8 + lrit;
    const int b_n  = wn * 32 + (ltile >> 1) * 8;

    float4 pa[4], pb[4];
#pragma unroll
    for (int i = 0; i < 4; i++) {
        int f = tid + i * 256;
        int row = f >> 3;
        int kc4 = (f & 7) * 4;
        int r = bm0 + row;
        pa[i] = (r < M) ? *(const float4*)(A + (size_t)r * K + kc4)
                        : make_float4(0.f, 0.f, 0.f, 0.f);
        int kr = f >> 5;
        int n4 = (f & 31) * 4;
        pb[i] = *(const float4*)(Bm + (size_t)kr * N + bn0 + n4);
    }

    for (int k0 = 0; k0 < K; k0 += 32) {
        // store staged regs to smem as half (straight copy, no transpose)
#pragma unroll
        for (int i = 0; i < 4; i++) {
            int f = tid + i * 256;
            int row = f >> 3;
            int kc4 = (f & 7) * 4;
            uint2 av;
            av.x = pack_h2(pa[i].x, pa[i].y);
            av.y = pack_h2(pa[i].z, pa[i].w);
            *(uint2*)&As[row][kc4] = av;
            int kr = f >> 5;
            int n4 = (f & 31) * 4;
            uint2 bv;
            bv.x = pack_h2(pb[i].x, pb[i].y);
            bv.y = pack_h2(pb[i].z, pb[i].w);
            *(uint2*)&Bs[kr][n4] = bv;
        }
        __syncthreads();

        if (k0 + 32 < K) {
#pragma unroll
            for (int i = 0; i < 4; i++) {
                int f = tid + i * 256;
                int row = f >> 3;
                int kc4 = (f & 7) * 4;
                int r = bm0 + row;
                pa[i] = (r < M) ? *(const float4*)(A + (size_t)r * K + k0 + 32 + kc4)
                                : make_float4(0.f, 0.f, 0.f, 0.f);
                int kr = f >> 5;
                int n4 = (f & 31) * 4;
                pb[i] = *(const float4*)(Bm + (size_t)(k0 + 32 + kr) * N + bn0 + n4);
            }
        }

#pragma unroll
        for (int kk = 0; kk < 32; kk += 16) {
            uint32_t af[4][4], bf[4][2];
#pragma unroll
            for (int mt = 0; mt < 4; mt++)
                ldmx4(af[mt], &As[a_m + mt * 16][kk + a_kc]);
#pragma unroll
            for (int p = 0; p < 2; p++) {
                uint32_t br[4];
                ldmx4t(br, &Bs[kk + b_k][b_n + p * 16]);
                bf[2 * p][0]     = br[0];
                bf[2 * p][1]     = br[1];
                bf[2 * p + 1][0] = br[2];
                bf[2 * p + 1][1] = br[3];
            }
#pragma unroll
            for (int mt = 0; mt < 4; mt++)
#pragma unroll
                for (int nt = 0; nt < 4; nt++)
                    mma_f16(acc[mt][nt], af[mt], bf[nt]);
        }
        __syncthreads();
    }

    const int row0 = bm0 + wm * 64 + (lane >> 2);
    const int col0 = bn0 + wn * 32 + 2 * (lane & 3);
#pragma unroll
    for (int mt = 0; mt < 4; mt++) {
#pragma unroll
        for (int nt = 0; nt < 4; nt++) {
            int r = row0 + mt * 16;
            int c = col0 + nt * 8;
            float v0 = acc[mt][nt][0], v1 = acc[mt][nt][1];
            float v2 = acc[mt][nt][2], v3 = acc[mt][nt][3];
            if (EPI) {
                float b0v = bias[c], b1v = bias[c + 1];
                if (r < M) {
                    float2 rr = *(const float2*)(resid + (size_t)r * N + c);
                    v0 += b0v + rr.x; v1 += b1v + rr.y;
                }
                if (r + 8 < M) {
                    float2 rr = *(const float2*)(resid + (size_t)(r + 8) * N + c);
                    v2 += b0v + rr.x; v3 += b1v + rr.y;
                }
            }
            if (r < M) { float2 o; o.x = v0; o.y = v1; *(float2*)(Cm + (size_t)r * N + c) = o; }
            if (r + 8 < M) { float2 o; o.x = v2; o.y = v3; *(float2*)(Cm + (size_t)(r + 8) * N + c) = o; }
        }
    }
}

// ---------------- attention pass 1 ----------------
__global__ __launch_bounds__(128) void attn1_k(
    const float* __restrict__ q, const float* __restrict__ kk,
    float* __restrict__ probs, float* __restrict__ rowinv, float* __restrict__ tokpart)
{
    const int b = blockIdx.z, h = blockIdx.y;
    const int tid = threadIdx.x;
    const int s = blockIdx.x * 128 + tid;
    __shared__ float ks[T_ * D_];
    __shared__ float tpw[4][T_];
    const int w = tid >> 5, lane = tid & 31;

    for (int i = tid; i < T_ * (D_ / 4); i += 128) {
        int t = i >> 4, d4 = (i & 15);
        *(float4*)&ks[t * D_ + d4 * 4] =
            *(const float4*)&kk[((size_t)(b * T_ + t)) * HD_ + h * D_ + d4 * 4];
    }
    for (int i = lane; i < T_; i += 32) tpw[w][i] = 0.f;
    __syncthreads();

    float4 q4[16];
    const float4* qp = (const float4*)(q + ((size_t)(b * S_) + s) * HD_ + h * D_);
#pragma unroll
    for (int j = 0; j < 16; j++) q4[j] = qp[j];

    const size_t pbase = (((size_t)(b * H_) + h) * S_ + s) * T_;
    float ssum = 0.f;
    for (int t = 0; t < T_; t++) {
        const float4* kp = (const float4*)&ks[t * D_];
        float l0 = 0.f, l1 = 0.f, l2 = 0.f, l3 = 0.f;
#pragma unroll
        for (int j = 0; j < 16; j++) {
            float4 kv = kp[j];
            l0 += q4[j].x * kv.x;
            l1 += q4[j].y * kv.y;
            l2 += q4[j].z * kv.z;
            l3 += q4[j].w * kv.w;
        }
        float e = __expf(((l0 + l1) + (l2 + l3)) * SCALE_);
        ssum += e;
        probs[pbase + t] = e;
    }
    const float inv = 1.f / ssum;
    rowinv[(size_t)(b * H_ + h) * S_ + s] = inv;
    for (int t = 0; t < T_; t++) {
        float p = probs[pbase + t] * inv;
#pragma unroll
        for (int o = 16; o; o >>= 1) p += __shfl_xor_sync(0xffffffffu, p, o);
        if (lane == 0) tpw[w][t] += p;
    }
    __syncthreads();
    if (tid < T_) {
        int lin = (b * H_ + h) * SCHUNK_ + blockIdx.x;
        tokpart[(size_t)lin * T_ + tid] = tpw[0][tid] + tpw[1][tid] + tpw[2][tid] + tpw[3][tid];
    }
}

// ---------------- token score reduce + top-k ----------------
__global__ void tok_reduce_k(const float* __restrict__ tokpart, float* __restrict__ scores)
{
    int idx = blockIdx.x * blockDim.x + threadIdx.x;
    if (idx >= B_ * T_) return;
    int b = idx / T_, t = idx % T_;
    float sum = 0.f;
    for (int h = 0; h < H_; h++)
        for (int c = 0; c < SCHUNK_; c++)
            sum += tokpart[(size_t)((b * H_ + h) * SCHUNK_ + c) * T_ + t];
    scores[idx] = sum * (1.f / (float)(H_ * S_));
}

__global__ void tok_topk_k(const float* __restrict__ scores, int* __restrict__ mask)
{
    int b = blockIdx.x, tid = threadIdx.x;
    __shared__ float sc[T_];
    if (tid < T_) sc[tid] = scores[b * T_ + tid];
    __syncthreads();
    if (tid < T_) {
        float v = sc[tid];
        int rank = 0;
        for (int j = 0; j < T_; j++) {
            float u = sc[j];
            rank += (int)((u > v) || (u == v && j < tid));
        }
        mask[b * T_ + tid] = (rank < KTOK_) ? 1 : 0;
    }
}

// ---------------- position scores + top-k ----------------
__global__ __launch_bounds__(256) void pos_scores_k(
    const float* __restrict__ probs, const float* __restrict__ rowinv,
    const int* __restrict__ tokmask, float* __restrict__ out)
{
    const int b = blockIdx.y;
    const int s = blockIdx.x * 256 + threadIdx.x;
    __shared__ float msk[T_];
    if (threadIdx.x < T_) msk[threadIdx.x] = (float)tokmask[b * T_ + threadIdx.x];
    __syncthreads();
    float sum = 0.f;
    for (int h = 0; h < H_; h++) {
        const float* p = probs + (((size_t)(b * H_) + h) * S_ + s) * T_;
        float part = 0.f;
        for (int t = 0; t < T_; t++) part += p[t] * msk[t];
        sum += part * rowinv[(size_t)(b * H_ + h) * S_ + s];
    }
    out[b * S_ + s] = sum * (1.f / (float)H_);
}

__global__ __launch_bounds__(256) void pos_topk_k(const float* __restrict__ scores, int* __restrict__ mask)
{
    const int b = blockIdx.y;
    __shared__ float sc[S_];
    for (int i = threadIdx.x; i < S_; i += 256) sc[i] = scores[b * S_ + i];
    __syncthreads();
    const int i = blockIdx.x * 256 + threadIdx.x;
    float v = sc[i];
    int rank = 0;
    for (int j = 0; j < S_; j++) {
        float u = sc[j];
        rank += (int)((u > v) || (u == v && j < i));
    }
    mask[b * S_ + i] = (rank < KPOS_) ? 1 : 0;
}

// ---------------- cross-frame K/V mixing ----------------
__global__ void kvmix_k(const float* __restrict__ kin, const float* __restrict__ vin,
                        const int* __restrict__ tokmask,
                        float* __restrict__ k2, float* __restrict__ v2)
{
    int idx = blockIdx.x * blockDim.x + threadIdx.x;
    if (idx >= T_ * HD_) return;
    int t = idx / HD_;
    int c = idx % HD_;
    float kv[B_], vv[B_];
    float ksum = 0.f, vsum = 0.f;
#pragma unroll
    for (int b = 0; b < B_; b++) {
        size_t off = ((size_t)(b * T_) + t) * HD_ + c;
        kv[b] = kin[off];
        vv[b] = vin[off];
        ksum += kv[b];
        vsum += vv[b];
    }
#pragma unroll
    for (int b = 0; b < B_; b++) {
        float tm = tokmask[b * T_ + t] ? STRENGTH_ : 0.f;
        size_t off = ((size_t)(b * T_) + t) * HD_ + c;
        float x  = kv[b];
        float mo = (ksum - x) * (1.f / (float)(B_ - 1));
        float mixed = ALPHA_ * x + (1.f - ALPHA_) * mo;
        k2[off] = x + tm * (mixed - x);
        x  = vv[b];
        mo = (vsum - x) * (1.f / (float)(B_ - 1));
        mixed = ALPHA_ * x + (1.f - ALPHA_) * mo;
        v2[off] = x + tm * (mixed - x);
    }
}

// ---------------- attention pass 2 ----------------
__global__ __launch_bounds__(128) void attn2_k(
    const float* __restrict__ q, const float* __restrict__ k2,
    const float* __restrict__ v2, float* __restrict__ ctx)
{
    const int b = blockIdx.z, h = blockIdx.y;
    const int tid = threadIdx.x;
    const int s = blockIdx.x * 128 + tid;
    __shared__ float ks[T_ * D_];
    __shared__ float vs[T_ * D_];
    for (int i = tid; i < T_ * (D_ / 4); i += 128) {
        int t = i >> 4, d4 = (i & 15);
        size_t off = ((size_t)(b * T_) + t) * HD_ + h * D_ + d4 * 4;
        *(float4*)&ks[t * D_ + d4 * 4] = *(const float4*)&k2[off];
        *(float4*)&vs[t * D_ + d4 * 4] = *(const float4*)&v2[off];
    }
    __syncthreads();

    float4 q4[16];
    const float4* qp = (const float4*)(q + ((size_t)(b * S_) + s) * HD_ + h * D_);
#pragma unroll
    for (int j = 0; j < 16; j++) q4[j] = qp[j];

    float ssum = 0.f;
    float4 cacc[16];
#pragma unroll
    for (int j = 0; j < 16; j++) cacc[j] = make_float4(0.f, 0.f, 0.f, 0.f);

    for (int t = 0; t < T_; t++) {
        const float4* kp = (const float4*)&ks[t * D_];
        float l0 = 0.f, l1 = 0.f, l2 = 0.f, l3 = 0.f;
#pragma unroll
        for (int j = 0; j < 16; j++) {
            float4 kv = kp[j];
            l0 += q4[j].x * kv.x;
            l1 += q4[j].y * kv.y;
            l2 += q4[j].z * kv.z;
            l3 += q4[j].w * kv.w;
        }
        float e = __expf(((l0 + l1) + (l2 + l3)) * SCALE_);
        ssum += e;
        const float4* vp = (const float4*)&vs[t * D_];
#pragma unroll
        for (int j = 0; j < 16; j++) {
            float4 vv = vp[j];
            cacc[j].x += e * vv.x;
            cacc[j].y += e * vv.y;
            cacc[j].z += e * vv.z;
            cacc[j].w += e * vv.w;
        }
    }
    float inv = 1.f / ssum;
    float4* cp = (float4*)(ctx + ((size_t)(b * S_) + s) * HD_ + h * D_);
#pragma unroll
    for (int j = 0; j < 16; j++) {
        float4 o;
        o.x = cacc[j].x * inv; o.y = cacc[j].y * inv;
        o.z = cacc[j].z * inv; o.w = cacc[j].w * inv;
        cp[j] = o;
    }
}

// ---------------- fused context batch-sum + patch injection ----------------
__global__ __launch_bounds__(256) void inject_fused_k(
    float* __restrict__ ctx, const int* __restrict__ posmask)
{
    const int i4 = blockIdx.x * 256 + threadIdx.x;     // index into S_*HD_/4
    if (i4 >= S_ * HD_ / 4) return;
    const size_t base = (size_t)i4 * 4;
    const int s = (int)(base / HD_);

    float4 v[B_];
    float4 sum = make_float4(0.f, 0.f, 0.f, 0.f);
#pragma unroll
    for (int b = 0; b < B_; b++) {
        v[b] = *(const float4*)(ctx + (size_t)b * S_ * HD_ + base);
        sum.x += v[b].x; sum.y += v[b].y; sum.z += v[b].z; sum.w += v[b].w;
    }
#pragma unroll
    for (int b = 0; b < B_; b++) {
        if (posmask[b * S_ + s]) {
            const float c7 = 1.f / (float)(B_ - 1);
            float4 o;
            o.x = v[b].x + WINJ_ * ((sum.x - v[b].x) * c7 - v[b].x);
            o.y = v[b].y + WINJ_ * ((sum.y - v[b].y) * c7 - v[b].y);
            o.z = v[b].z + WINJ_ * ((sum.z - v[b].z) * c7 - v[b].z);
            o.w = v[b].w + WINJ_ * ((sum.w - v[b].w) * c7 - v[b].w);
            *(float4*)(ctx + (size_t)b * S_ * HD_ + base) = o;
        }
    }
}

// ---------------- launch ----------------
extern "C" void kernel_launch(void* const* d_in, const int* in_sizes, int n_in,
                              void* d_out, int out_size)
{
    (void)in_sizes; (void)n_in; (void)out_size;
    const float* X  = (const float*)d_in[0];
    const float* E  = (const float*)d_in[1];
    const float* Wq = (const float*)d_in[2];
    const float* Wk = (const float*)d_in[3];
    const float* Wv = (const float*)d_in[4];
    const float* Wo = (const float*)d_in[5];
    const float* bo = (const float*)d_in[6];
    float* out = (float*)d_out;

    float *q, *k, *v, *k2, *v2, *probs, *rowinv, *tokpart, *tokscores, *posscores, *ctx;
    int *tokmask, *posmask;
    cudaGetSymbolAddress((void**)&q,        g_q);
    cudaGetSymbolAddress((void**)&k,        g_k);
    cudaGetSymbolAddress((void**)&v,        g_v);
    cudaGetSymbolAddress((void**)&k2,       g_k2);
    cudaGetSymbolAddress((void**)&v2,       g_v2);
    cudaGetSymbolAddress((void**)&probs,    g_probs);
    cudaGetSymbolAddress((void**)&rowinv,   g_rowinv);
    cudaGetSymbolAddress((void**)&tokpart,  g_tokpart);
    cudaGetSymbolAddress((void**)&tokscores,g_tokscores);
    cudaGetSymbolAddress((void**)&tokmask,  g_tokmask);
    cudaGetSymbolAddress((void**)&posscores,g_posscores);
    cudaGetSymbolAddress((void**)&posmask,  g_posmask);
    cudaGetSymbolAddress((void**)&ctx,      g_ctx);

    // 1. projections (fp16 tensor cores, ldmatrix fragment loads)
    h16gemm_k<0><<<dim3(HD_ / 128, (B_ * S_) / 128), 256>>>(X, Wq, q, B_ * S_, HD_, C_, nullptr, nullptr);
    h16gemm_k<0><<<dim3(HD_ / 128, (B_ * T_ + 127) / 128), 256>>>(E, Wk, k, B_ * T_, HD_, CE_, nullptr, nullptr);
    h16gemm_k<0><<<dim3(HD_ / 128, (B_ * T_ + 127) / 128), 256>>>(E, Wv, v, B_ * T_, HD_, CE_, nullptr, nullptr);

    // 2. first attention pass -> e + inv + token partial sums
    attn1_k<<<dim3(SCHUNK_, H_, B_), 128>>>(q, k, probs, rowinv, tokpart);
    tok_reduce_k<<<(B_ * T_ + 255) / 256, 256>>>(tokpart, tokscores);
    tok_topk_k<<<B_, 128>>>(tokscores, tokmask);

    // 3. position scores + top-k
    pos_scores_k<<<dim3(S_ / 256, B_), 256>>>(probs, rowinv, tokmask, posscores);
    pos_topk_k<<<dim3(S_ / 256, B_), 256>>>(posscores, posmask);

    // 4. cross-frame K/V mixing
    kvmix_k<<<(T_ * HD_ + 255) / 256, 256>>>(k, v, tokmask, k2, v2);

    // 5. second attention pass -> context
    attn2_k<<<dim3(SCHUNK_, H_, B_), 128>>>(q, k2, v2, ctx);

    // 6. fused batch-sum + patch correspondence injection
    inject_fused_k<<<(S_ * HD_ / 4 + 255) / 256, 256>>>(ctx, posmask);

    // 7. output projection + bias + residual
    h16gemm_k<1><<<dim3(HD_ / 128, (B_ * S_) / 128), 256>>>(ctx, Wo, out, B_ * S_, HD_, C_, bo, X);
}

// round 7
// speedup vs baseline: 5.5990x; 1.5053x over previous
#include <cuda_runtime.h>
#include <cuda_fp16.h>
#include <math.h>
#include <stdint.h>

#define B_  8
#define S_  4096
#define T_  77
#define TP_ 80            // padded T
#define C_  1280
#define CE_ 2048
#define H_  20
#define D_  64
#define HD_ 1280
#define KTOK_ 12
#define KPOS_ 1229
#define SCHUNK_ (S_/128)   // 32

#define SCALE_ 0.125f
#define STRENGTH_ 0.5f
#define ALPHA_ 0.7f
#define WINJ_ 0.25f        // FIW * STRENGTH

// ---------------- scratch (device globals; no allocations) ----------------
__device__ float g_q[(size_t)B_*S_*HD_];
__device__ float g_k[B_*T_*HD_];
__device__ float g_v[B_*T_*HD_];
__device__ float g_k2[B_*T_*HD_];
__device__ float g_v2[B_*T_*HD_];
__device__ float g_probs[(size_t)B_*H_*S_*TP_];   // NORMALIZED probs, pitch 80
__device__ float g_tokpart[B_*H_*SCHUNK_*T_];
__device__ float g_tokscores[B_*T_];
__device__ int   g_tokmask[B_*T_];
__device__ float g_posscores[B_*S_];
__device__ int   g_posmask[B_*S_];
__device__ float g_ctx[(size_t)B_*S_*HD_];

// ---------------- mma helpers ----------------
__device__ __forceinline__ void mma_f16(float* c, const uint32_t* a, const uint32_t* b) {
    asm volatile(
        "mma.sync.aligned.m16n8k16.row.col.f32.f16.f16.f32 "
        "{%0,%1,%2,%3},{%4,%5,%6,%7},{%8,%9},{%0,%1,%2,%3};"
        : "+f"(c[0]), "+f"(c[1]), "+f"(c[2]), "+f"(c[3])
        : "r"(a[0]), "r"(a[1]), "r"(a[2]), "r"(a[3]), "r"(b[0]), "r"(b[1]));
}
__device__ __forceinline__ void ldmx4(uint32_t* r, const void* p) {
    uint32_t a = (uint32_t)__cvta_generic_to_shared(p);
    asm volatile("ldmatrix.sync.aligned.m8n8.x4.shared.b16 {%0,%1,%2,%3}, [%4];"
                 : "=r"(r[0]), "=r"(r[1]), "=r"(r[2]), "=r"(r[3]) : "r"(a));
}
__device__ __forceinline__ void ldmx4t(uint32_t* r, const void* p) {
    uint32_t a = (uint32_t)__cvta_generic_to_shared(p);
    asm volatile("ldmatrix.sync.aligned.m8n8.x4.trans.shared.b16 {%0,%1,%2,%3}, [%4];"
                 : "=r"(r[0]), "=r"(r[1]), "=r"(r[2]), "=r"(r[3]) : "r"(a));
}
__device__ __forceinline__ uint32_t pack_h2(float x, float y) {
    __half2 h = __floats2half2_rn(x, y);
    return *(uint32_t*)&h;
}

// ====================================================================
//  fp16 mma.sync GEMM : 128x128x32 tiles, 256 threads (unchanged from R5)
// ====================================================================
#define AKP_ 40
#define BNP_ 136

template<int EPI>
__global__ __launch_bounds__(256) void h16gemm_k(
    const float* __restrict__ A, const float* __restrict__ Bm, float* __restrict__ Cm,
    int M, int N, int K,
    const float* __restrict__ bias, const float* __restrict__ resid)
{
    __shared__ __half As[128][AKP_];
    __shared__ __half Bs[32][BNP_];

    const int tid  = threadIdx.x;
    const int wid  = tid >> 5, lane = tid & 31;
    const int wm   = wid & 1;
    const int wn   = wid >> 1;
    const int bm0  = blockIdx.y * 128;
    const int bn0  = blockIdx.x * 128;

    float acc[4][4][4];
#pragma unroll
    for (int i = 0; i < 4; i++)
#pragma unroll
        for (int j = 0; j < 4; j++)
#pragma unroll
            for (int r = 0; r < 4; r++) acc[i][j][r] = 0.f;

    const int ltile = lane >> 3, lrit = lane & 7;
    const int a_m  = wm * 64 + (ltile & 1) * 8 + lrit;
    const int a_kc = (ltile >> 1) * 8;
    const int b_k  = (ltile & 1) * 8 + lrit;
    const int b_n  = wn * 32 + (ltile >> 1) * 8;

    float4 pa[4], pb[4];
#pragma unroll
    for (int i = 0; i < 4; i++) {
        int f = tid + i * 256;
        int row = f >> 3;
        int kc4 = (f & 7) * 4;
        int r = bm0 + row;
        pa[i] = (r < M) ? *(const float4*)(A + (size_t)r * K + kc4)
                        : make_float4(0.f, 0.f, 0.f, 0.f);
        int kr = f >> 5;
        int n4 = (f & 31) * 4;
        pb[i] = *(const float4*)(Bm + (size_t)kr * N + bn0 + n4);
    }

    for (int k0 = 0; k0 < K; k0 += 32) {
#pragma unroll
        for (int i = 0; i < 4; i++) {
            int f = tid + i * 256;
            int row = f >> 3;
            int kc4 = (f & 7) * 4;
            uint2 av;
            av.x = pack_h2(pa[i].x, pa[i].y);
            av.y = pack_h2(pa[i].z, pa[i].w);
            *(uint2*)&As[row][kc4] = av;
            int kr = f >> 5;
            int n4 = (f & 31) * 4;
            uint2 bv;
            bv.x = pack_h2(pb[i].x, pb[i].y);
            bv.y = pack_h2(pb[i].z, pb[i].w);
            *(uint2*)&Bs[kr][n4] = bv;
        }
        __syncthreads();

        if (k0 + 32 < K) {
#pragma unroll
            for (int i = 0; i < 4; i++) {
                int f = tid + i * 256;
                int row = f >> 3;
                int kc4 = (f & 7) * 4;
                int r = bm0 + row;
                pa[i] = (r < M) ? *(const float4*)(A + (size_t)r * K + k0 + 32 + kc4)
                                : make_float4(0.f, 0.f, 0.f, 0.f);
                int kr = f >> 5;
                int n4 = (f & 31) * 4;
                pb[i] = *(const float4*)(Bm + (size_t)(k0 + 32 + kr) * N + bn0 + n4);
            }
        }

#pragma unroll
        for (int kk = 0; kk < 32; kk += 16) {
            uint32_t af[4][4], bf[4][2];
#pragma unroll
            for (int mt = 0; mt < 4; mt++)
                ldmx4(af[mt], &As[a_m + mt * 16][kk + a_kc]);
#pragma unroll
            for (int p = 0; p < 2; p++) {
                uint32_t br[4];
                ldmx4t(br, &Bs[kk + b_k][b_n + p * 16]);
                bf[2 * p][0]     = br[0];
                bf[2 * p][1]     = br[1];
                bf[2 * p + 1][0] = br[2];
                bf[2 * p + 1][1] = br[3];
            }
#pragma unroll
            for (int mt = 0; mt < 4; mt++)
#pragma unroll
                for (int nt = 0; nt < 4; nt++)
                    mma_f16(acc[mt][nt], af[mt], bf[nt]);
        }
        __syncthreads();
    }

    const int row0 = bm0 + wm * 64 + (lane >> 2);
    const int col0 = bn0 + wn * 32 + 2 * (lane & 3);
#pragma unroll
    for (int mt = 0; mt < 4; mt++) {
#pragma unroll
        for (int nt = 0; nt < 4; nt++) {
            int r = row0 + mt * 16;
            int c = col0 + nt * 8;
            float v0 = acc[mt][nt][0], v1 = acc[mt][nt][1];
            float v2 = acc[mt][nt][2], v3 = acc[mt][nt][3];
            if (EPI) {
                float b0v = bias[c], b1v = bias[c + 1];
                if (r < M) {
                    float2 rr = *(const float2*)(resid + (size_t)r * N + c);
                    v0 += b0v + rr.x; v1 += b1v + rr.y;
                }
                if (r + 8 < M) {
                    float2 rr = *(const float2*)(resid + (size_t)(r + 8) * N + c);
                    v2 += b0v + rr.x; v3 += b1v + rr.y;
                }
            }
            if (r < M) { float2 o; o.x = v0; o.y = v1; *(float2*)(Cm + (size_t)r * N + c) = o; }
            if (r + 8 < M) { float2 o; o.x = v2; o.y = v3; *(float2*)(Cm + (size_t)(r + 8) * N + c) = o; }
        }
    }
}

// ====================================================================
//  attention pass 1 : tensor-core logits -> softmax -> probs + tokpart
//  block = 128 s-rows of one (b,h); 4 warps, warp tile 32x80
// ====================================================================
#define QP_  72   // Q smem pitch (halves) : 64 + 8
#define KP2_ 88   // K smem [k][t] pitch (halves): 80 + 8
#define PP_  88   // Ps fp32/fp16 pitch
#define A1_QS 0
#define A1_KS (128 * QP_ * 2)                 // 18432
#define A1_SMEM_A (A1_KS + 64 * KP2_ * 2)     // 29696 (phase A size)
#define A1_SMEM (128 * PP_ * 4 > A1_SMEM_A ? 128 * PP_ * 4 : A1_SMEM_A)  // 45056

__global__ __launch_bounds__(128) void attn1_k(
    const float* __restrict__ q, const float* __restrict__ kk,
    float* __restrict__ probs, float* __restrict__ tokpart)
{
    extern __shared__ char dsm[];
    __half* Qs = (__half*)(dsm + A1_QS);
    __half* Ks = (__half*)(dsm + A1_KS);
    float*  Ps = (float*)dsm;                  // phase B alias

    const int b = blockIdx.z, h = blockIdx.y;
    const int tid = threadIdx.x;
    const int wid = tid >> 5, lane = tid & 31;
    const int bm0 = blockIdx.x * 128;

    // load Q tile (128 x 64) fp32 -> fp16 [m][k]
#pragma unroll
    for (int i = 0; i < 16; i++) {
        int f = tid + i * 128;
        int row = f >> 4, c4 = (f & 15) * 4;
        float4 v = *(const float4*)(q + ((size_t)(b * S_) + bm0 + row) * HD_ + h * D_ + c4);
        uint2 av;
        av.x = pack_h2(v.x, v.y);
        av.y = pack_h2(v.z, v.w);
        *(uint2*)&Qs[row * QP_ + c4] = av;
    }
    // zero K smem (64 x 88 halves)
    for (int f = tid; f < 64 * KP2_ / 2; f += 128) ((uint32_t*)Ks)[f] = 0;
    __syncthreads();
    // load K (77 x 64) transposed -> Ks[k][t]
    for (int f = tid; f < T_ * 16; f += 128) {
        int t = f >> 4, d4 = (f & 15) * 4;
        float4 v = *(const float4*)(kk + ((size_t)(b * T_) + t) * HD_ + h * D_ + d4);
        Ks[(d4 + 0) * KP2_ + t] = __float2half_rn(v.x);
        Ks[(d4 + 1) * KP2_ + t] = __float2half_rn(v.y);
        Ks[(d4 + 2) * KP2_ + t] = __float2half_rn(v.z);
        Ks[(d4 + 3) * KP2_ + t] = __float2half_rn(v.w);
    }
    __syncthreads();

    const int ltile = lane >> 3, lrit = lane & 7;
    const int a_m  = wid * 32 + (ltile & 1) * 8 + lrit;
    const int a_kc = (ltile >> 1) * 8;
    const int b_k  = (ltile & 1) * 8 + lrit;
    const int b_n  = (ltile >> 1) * 8;

    float acc[2][10][4];
#pragma unroll
    for (int mt = 0; mt < 2; mt++)
#pragma unroll
        for (int nt = 0; nt < 10; nt++)
#pragma unroll
            for (int r = 0; r < 4; r++) acc[mt][nt][r] = 0.f;

#pragma unroll
    for (int kkk = 0; kkk < 64; kkk += 16) {
        uint32_t af[2][4], bf[10][2];
#pragma unroll
        for (int mt = 0; mt < 2; mt++)
            ldmx4(af[mt], &Qs[(a_m + mt * 16) * QP_ + kkk + a_kc]);
#pragma unroll
        for (int p = 0; p < 5; p++) {
            uint32_t br[4];
            ldmx4t(br, &Ks[(kkk + b_k) * KP2_ + b_n + p * 16]);
            bf[2 * p][0]     = br[0];
            bf[2 * p][1]     = br[1];
            bf[2 * p + 1][0] = br[2];
            bf[2 * p + 1][1] = br[3];
        }
#pragma unroll
        for (int mt = 0; mt < 2; mt++)
#pragma unroll
            for (int nt = 0; nt < 10; nt++)
                mma_f16(acc[mt][nt], af[mt], bf[nt]);
    }

    // exp + row sums (registers only)
    float rs_a[2] = {0.f, 0.f}, rs_b[2] = {0.f, 0.f};
#pragma unroll
    for (int mt = 0; mt < 2; mt++) {
#pragma unroll
        for (int nt = 0; nt < 10; nt++) {
            int col = nt * 8 + 2 * (lane & 3);
            float e0 = (col     < T_) ? __expf(acc[mt][nt][0] * SCALE_) : 0.f;
            float e1 = (col + 1 < T_) ? __expf(acc[mt][nt][1] * SCALE_) : 0.f;
            float e2 = (col     < T_) ? __expf(acc[mt][nt][2] * SCALE_) : 0.f;
            float e3 = (col + 1 < T_) ? __expf(acc[mt][nt][3] * SCALE_) : 0.f;
            acc[mt][nt][0] = e0; acc[mt][nt][1] = e1;
            acc[mt][nt][2] = e2; acc[mt][nt][3] = e3;
            rs_a[mt] += e0 + e1;
            rs_b[mt] += e2 + e3;
        }
        rs_a[mt] += __shfl_xor_sync(0xffffffffu, rs_a[mt], 1);
        rs_a[mt] += __shfl_xor_sync(0xffffffffu, rs_a[mt], 2);
        rs_b[mt] += __shfl_xor_sync(0xffffffffu, rs_b[mt], 1);
        rs_b[mt] += __shfl_xor_sync(0xffffffffu, rs_b[mt], 2);
    }
    float inv_a[2] = {1.f / rs_a[0], 1.f / rs_a[1]};
    float inv_b[2] = {1.f / rs_b[0], 1.f / rs_b[1]};

    __syncthreads();   // done reading Qs/Ks; Ps may overwrite

    const size_t rowbase = ((size_t)(b * H_) + h) * S_ + bm0;
#pragma unroll
    for (int mt = 0; mt < 2; mt++) {
        int r = wid * 32 + mt * 16 + (lane >> 2);
#pragma unroll
        for (int nt = 0; nt < 10; nt++) {
            int col = nt * 8 + 2 * (lane & 3);
            float2 pA; pA.x = acc[mt][nt][0] * inv_a[mt]; pA.y = acc[mt][nt][1] * inv_a[mt];
            float2 pB; pB.x = acc[mt][nt][2] * inv_b[mt]; pB.y = acc[mt][nt][3] * inv_b[mt];
            *(float2*)&Ps[r * PP_ + col]       = pA;
            *(float2*)&Ps[(r + 8) * PP_ + col] = pB;
            *(float2*)(probs + (rowbase + r) * TP_ + col)     = pA;
            *(float2*)(probs + (rowbase + r + 8) * TP_ + col) = pB;
        }
    }
    __syncthreads();

    if (tid < T_) {
        float sum = 0.f;
#pragma unroll 4
        for (int r = 0; r < 128; r++) sum += Ps[r * PP_ + tid];
        int lin = (b * H_ + h) * SCHUNK_ + blockIdx.x;
        tokpart[(size_t)lin * T_ + tid] = sum;
    }
}

// ---------------- token score reduce + top-k ----------------
__global__ void tok_reduce_k(const float* __restrict__ tokpart, float* __restrict__ scores)
{
    int idx = blockIdx.x * blockDim.x + threadIdx.x;
    if (idx >= B_ * T_) return;
    int b = idx / T_, t = idx % T_;
    float sum = 0.f;
    for (int h = 0; h < H_; h++)
        for (int c = 0; c < SCHUNK_; c++)
            sum += tokpart[(size_t)((b * H_ + h) * SCHUNK_ + c) * T_ + t];
    scores[idx] = sum * (1.f / (float)(H_ * S_));
}

__global__ void tok_topk_k(const float* __restrict__ scores, int* __restrict__ mask)
{
    int b = blockIdx.x, tid = threadIdx.x;
    __shared__ float sc[T_];
    if (tid < T_) sc[tid] = scores[b * T_ + tid];
    __syncthreads();
    if (tid < T_) {
        float v = sc[tid];
        int rank = 0;
        for (int j = 0; j < T_; j++) {
            float u = sc[j];
            rank += (int)((u > v) || (u == v && j < tid));
        }
        mask[b * T_ + tid] = (rank < KTOK_) ? 1 : 0;
    }
}

// ---------------- position scores (vectorized) + top-k ----------------
__global__ __launch_bounds__(256) void pos_scores_k(
    const float* __restrict__ probs, const int* __restrict__ tokmask, float* __restrict__ out)
{
    const int b = blockIdx.y;
    const int s = blockIdx.x * 256 + threadIdx.x;
    __shared__ float msk[TP_];
    if (threadIdx.x < TP_) msk[threadIdx.x] = (threadIdx.x < T_) ? (float)tokmask[b * T_ + threadIdx.x] : 0.f;
    __syncthreads();
    float sum = 0.f;
    for (int h = 0; h < H_; h++) {
        const float4* p = (const float4*)(probs + (((size_t)(b * H_) + h) * S_ + s) * TP_);
#pragma unroll
        for (int t4 = 0; t4 < TP_ / 4; t4++) {
            float4 v = p[t4];
            const float* m = &msk[t4 * 4];
            sum += v.x * m[0] + v.y * m[1] + v.z * m[2] + v.w * m[3];
        }
    }
    out[b * S_ + s] = sum * (1.f / (float)H_);
}

__global__ __launch_bounds__(256) void pos_topk_k(const float* __restrict__ scores, int* __restrict__ mask)
{
    const int b = blockIdx.y;
    __shared__ float sc[S_];
    for (int i = threadIdx.x; i < S_; i += 256) sc[i] = scores[b * S_ + i];
    __syncthreads();
    const int i = blockIdx.x * 256 + threadIdx.x;
    float v = sc[i];
    int rank = 0;
    for (int j = 0; j < S_; j++) {
        float u = sc[j];
        rank += (int)((u > v) || (u == v && j < i));
    }
    mask[b * S_ + i] = (rank < KPOS_) ? 1 : 0;
}

// ---------------- cross-frame K/V mixing ----------------
__global__ void kvmix_k(const float* __restrict__ kin, const float* __restrict__ vin,
                        const int* __restrict__ tokmask,
                        float* __restrict__ k2, float* __restrict__ v2)
{
    int idx = blockIdx.x * blockDim.x + threadIdx.x;
    if (idx >= T_ * HD_) return;
    int t = idx / HD_;
    int c = idx % HD_;
    float kv[B_], vv[B_];
    float ksum = 0.f, vsum = 0.f;
#pragma unroll
    for (int b = 0; b < B_; b++) {
        size_t off = ((size_t)(b * T_) + t) * HD_ + c;
        kv[b] = kin[off];
        vv[b] = vin[off];
        ksum += kv[b];
        vsum += vv[b];
    }
#pragma unroll
    for (int b = 0; b < B_; b++) {
        float tm = tokmask[b * T_ + t] ? STRENGTH_ : 0.f;
        size_t off = ((size_t)(b * T_) + t) * HD_ + c;
        float x  = kv[b];
        float mo = (ksum - x) * (1.f / (float)(B_ - 1));
        float mixed = ALPHA_ * x + (1.f - ALPHA_) * mo;
        k2[off] = x + tm * (mixed - x);
        x  = vv[b];
        mo = (vsum - x) * (1.f / (float)(B_ - 1));
        mixed = ALPHA_ * x + (1.f - ALPHA_) * mo;
        v2[off] = x + tm * (mixed - x);
    }
}

// ====================================================================
//  attention pass 2 : tensor-core logits -> softmax -> P(fp16) -> P·V
// ====================================================================
#define VP_  72   // V smem [t][d] pitch (halves)
#define A2_QS 0
#define A2_KS (128 * QP_ * 2)                   // 18432
#define A2_VS (A2_KS + 64 * KP2_ * 2)           // 29696
#define A2_PS (A2_VS + TP_ * VP_ * 2)           // 41216
#define A2_SMEM (A2_PS + 128 * PP_ * 2)         // 63744

__global__ __launch_bounds__(128) void attn2_k(
    const float* __restrict__ q, const float* __restrict__ k2,
    const float* __restrict__ v2, float* __restrict__ ctx)
{
    extern __shared__ char dsm[];
    __half* Qs = (__half*)(dsm + A2_QS);
    __half* Ks = (__half*)(dsm + A2_KS);
    __half* Vs = (__half*)(dsm + A2_VS);
    __half* Ph = (__half*)(dsm + A2_PS);

    const int b = blockIdx.z, h = blockIdx.y;
    const int tid = threadIdx.x;
    const int wid = tid >> 5, lane = tid & 31;
    const int bm0 = blockIdx.x * 128;

    // Q tile
#pragma unroll
    for (int i = 0; i < 16; i++) {
        int f = tid + i * 128;
        int row = f >> 4, c4 = (f & 15) * 4;
        float4 v = *(const float4*)(q + ((size_t)(b * S_) + bm0 + row) * HD_ + h * D_ + c4);
        uint2 av;
        av.x = pack_h2(v.x, v.y);
        av.y = pack_h2(v.z, v.w);
        *(uint2*)&Qs[row * QP_ + c4] = av;
    }
    // zero K2 + V smem
    for (int f = tid; f < 64 * KP2_ / 2; f += 128) ((uint32_t*)Ks)[f] = 0;
    for (int f = tid; f < TP_ * VP_ / 2; f += 128) ((uint32_t*)Vs)[f] = 0;
    __syncthreads();
    // K2 transposed [k][t]; V straight [t][d]
    for (int f = tid; f < T_ * 16; f += 128) {
        int t = f >> 4, d4 = (f & 15) * 4;
        float4 kv = *(const float4*)(k2 + ((size_t)(b * T_) + t) * HD_ + h * D_ + d4);
        Ks[(d4 + 0) * KP2_ + t] = __float2half_rn(kv.x);
        Ks[(d4 + 1) * KP2_ + t] = __float2half_rn(kv.y);
        Ks[(d4 + 2) * KP2_ + t] = __float2half_rn(kv.z);
        Ks[(d4 + 3) * KP2_ + t] = __float2half_rn(kv.w);
        float4 vv = *(const float4*)(v2 + ((size_t)(b * T_) + t) * HD_ + h * D_ + d4);
        uint2 av;
        av.x = pack_h2(vv.x, vv.y);
        av.y = pack_h2(vv.z, vv.w);
        *(uint2*)&Vs[t * VP_ + d4] = av;
    }
    __syncthreads();

    const int ltile = lane >> 3, lrit = lane & 7;
    const int a_m  = wid * 32 + (ltile & 1) * 8 + lrit;
    const int a_kc = (ltile >> 1) * 8;
    const int b_k  = (ltile & 1) * 8 + lrit;
    const int b_n  = (ltile >> 1) * 8;

    // ---- logits = Q K2^T ----
    float acc[2][10][4];
#pragma unroll
    for (int mt = 0; mt < 2; mt++)
#pragma unroll
        for (int nt = 0; nt < 10; nt++)
#pragma unroll
            for (int r = 0; r < 4; r++) acc[mt][nt][r] = 0.f;

#pragma unroll
    for (int kkk = 0; kkk < 64; kkk += 16) {
        uint32_t af[2][4], bf[10][2];
#pragma unroll
        for (int mt = 0; mt < 2; mt++)
            ldmx4(af[mt], &Qs[(a_m + mt * 16) * QP_ + kkk + a_kc]);
#pragma unroll
        for (int p = 0; p < 5; p++) {
            uint32_t br[4];
            ldmx4t(br, &Ks[(kkk + b_k) * KP2_ + b_n + p * 16]);
            bf[2 * p][0]     = br[0];
            bf[2 * p][1]     = br[1];
            bf[2 * p + 1][0] = br[2];
            bf[2 * p + 1][1] = br[3];
        }
#pragma unroll
        for (int mt = 0; mt < 2; mt++)
#pragma unroll
            for (int nt = 0; nt < 10; nt++)
                mma_f16(acc[mt][nt], af[mt], bf[nt]);
    }

    // exp + row sums
    float rs_a[2] = {0.f, 0.f}, rs_b[2] = {0.f, 0.f};
#pragma unroll
    for (int mt = 0; mt < 2; mt++) {
#pragma unroll
        for (int nt = 0; nt < 10; nt++) {
            int col = nt * 8 + 2 * (lane & 3);
            float e0 = (col     < T_) ? __expf(acc[mt][nt][0] * SCALE_) : 0.f;
            float e1 = (col + 1 < T_) ? __expf(acc[mt][nt][1] * SCALE_) : 0.f;
            float e2 = (col     < T_) ? __expf(acc[mt][nt][2] * SCALE_) : 0.f;
            float e3 = (col + 1 < T_) ? __expf(acc[mt][nt][3] * SCALE_) : 0.f;
            acc[mt][nt][0] = e0; acc[mt][nt][1] = e1;
            acc[mt][nt][2] = e2; acc[mt][nt][3] = e3;
            rs_a[mt] += e0 + e1;
            rs_b[mt] += e2 + e3;
        }
        rs_a[mt] += __shfl_xor_sync(0xffffffffu, rs_a[mt], 1);
        rs_a[mt] += __shfl_xor_sync(0xffffffffu, rs_a[mt], 2);
        rs_b[mt] += __shfl_xor_sync(0xffffffffu, rs_b[mt], 1);
        rs_b[mt] += __shfl_xor_sync(0xffffffffu, rs_b[mt], 2);
    }
    float inv_a[2] = {1.f / rs_a[0], 1.f / rs_a[1]};
    float inv_b[2] = {1.f / rs_b[0], 1.f / rs_b[1]};

    // store normalized P as fp16 [m][t]
#pragma unroll
    for (int mt = 0; mt < 2; mt++) {
        int r = wid * 32 + mt * 16 + (lane >> 2);
#pragma unroll
        for (int nt = 0; nt < 10; nt++) {
            int col = nt * 8 + 2 * (lane & 3);
            *(uint32_t*)&Ph[r * PP_ + col] =
                pack_h2(acc[mt][nt][0] * inv_a[mt], acc[mt][nt][1] * inv_a[mt]);
            *(uint32_t*)&Ph[(r + 8) * PP_ + col] =
                pack_h2(acc[mt][nt][2] * inv_b[mt], acc[mt][nt][3] * inv_b[mt]);
        }
    }
    __syncthreads();

    // ---- ctx = P V ----
    float acc2[2][8][4];
#pragma unroll
    for (int mt = 0; mt < 2; mt++)
#pragma unroll
        for (int nt = 0; nt < 8; nt++)
#pragma unroll
            for (int r = 0; r < 4; r++) acc2[mt][nt][r] = 0.f;

#pragma unroll
    for (int kkk = 0; kkk < TP_; kkk += 16) {
        uint32_t af[2][4], bf[8][2];
#pragma unroll
        for (int mt = 0; mt < 2; mt++)
            ldmx4(af[mt], &Ph[(a_m + mt * 16) * PP_ + kkk + a_kc]);
#pragma unroll
        for (int p = 0; p < 4; p++) {
            uint32_t br[4];
            ldmx4t(br, &Vs[(kkk + b_k) * VP_ + b_n + p * 16]);
            bf[2 * p][0]     = br[0];
            bf[2 * p][1]     = br[1];
            bf[2 * p + 1][0] = br[2];
            bf[2 * p + 1][1] = br[3];
        }
#pragma unroll
        for (int mt = 0; mt < 2; mt++)
#pragma unroll
            for (int nt = 0; nt < 8; nt++)
                mma_f16(acc2[mt][nt], af[mt], bf[nt]);
    }

    // write ctx
#pragma unroll
    for (int mt = 0; mt < 2; mt++) {
        int r = wid * 32 + mt * 16 + (lane >> 2);
#pragma unroll
        for (int nt = 0; nt < 8; nt++) {
            int col = nt * 8 + 2 * (lane & 3);
            float2 oA; oA.x = acc2[mt][nt][0]; oA.y = acc2[mt][nt][1];
            float2 oB; oB.x = acc2[mt][nt][2]; oB.y = acc2[mt][nt][3];
            *(float2*)(ctx + ((size_t)(b * S_) + bm0 + r) * HD_ + h * D_ + col)     = oA;
            *(float2*)(ctx + ((size_t)(b * S_) + bm0 + r + 8) * HD_ + h * D_ + col) = oB;
        }
    }
}

// ---------------- fused context batch-sum + patch injection ----------------
__global__ __launch_bounds__(256) void inject_fused_k(
    float* __restrict__ ctx, const int* __restrict__ posmask)
{
    const int i4 = blockIdx.x * 256 + threadIdx.x;
    if (i4 >= S_ * HD_ / 4) return;
    const size_t base = (size_t)i4 * 4;
    const int s = (int)(base / HD_);

    float4 v[B_];
    float4 sum = make_float4(0.f, 0.f, 0.f, 0.f);
#pragma unroll
    for (int b = 0; b < B_; b++) {
        v[b] = *(const float4*)(ctx + (size_t)b * S_ * HD_ + base);
        sum.x += v[b].x; sum.y += v[b].y; sum.z += v[b].z; sum.w += v[b].w;
    }
#pragma unroll
    for (int b = 0; b < B_; b++) {
        if (posmask[b * S_ + s]) {
            const float c7 = 1.f / (float)(B_ - 1);
            float4 o;
            o.x = v[b].x + WINJ_ * ((sum.x - v[b].x) * c7 - v[b].x);
            o.y = v[b].y + WINJ_ * ((sum.y - v[b].y) * c7 - v[b].y);
            o.z = v[b].z + WINJ_ * ((sum.z - v[b].z) * c7 - v[b].z);
            o.w = v[b].w + WINJ_ * ((sum.w - v[b].w) * c7 - v[b].w);
            *(float4*)(ctx + (size_t)b * S_ * HD_ + base) = o;
        }
    }
}

// ---------------- launch ----------------
extern "C" void kernel_launch(void* const* d_in, const int* in_sizes, int n_in,
                              void* d_out, int out_size)
{
    (void)in_sizes; (void)n_in; (void)out_size;
    const float* X  = (const float*)d_in[0];
    const float* E  = (const float*)d_in[1];
    const float* Wq = (const float*)d_in[2];
    const float* Wk = (const float*)d_in[3];
    const float* Wv = (const float*)d_in[4];
    const float* Wo = (const float*)d_in[5];
    const float* bo = (const float*)d_in[6];
    float* out = (float*)d_out;

    float *q, *k, *v, *k2, *v2, *probs, *tokpart, *tokscores, *posscores, *ctx;
    int *tokmask, *posmask;
    cudaGetSymbolAddress((void**)&q,        g_q);
    cudaGetSymbolAddress((void**)&k,        g_k);
    cudaGetSymbolAddress((void**)&v,        g_v);
    cudaGetSymbolAddress((void**)&k2,       g_k2);
    cudaGetSymbolAddress((void**)&v2,       g_v2);
    cudaGetSymbolAddress((void**)&probs,    g_probs);
    cudaGetSymbolAddress((void**)&tokpart,  g_tokpart);
    cudaGetSymbolAddress((void**)&tokscores,g_tokscores);
    cudaGetSymbolAddress((void**)&tokmask,  g_tokmask);
    cudaGetSymbolAddress((void**)&posscores,g_posscores);
    cudaGetSymbolAddress((void**)&posmask,  g_posmask);
    cudaGetSymbolAddress((void**)&ctx,      g_ctx);

    cudaFuncSetAttribute(attn1_k, cudaFuncAttributeMaxDynamicSharedMemorySize, A1_SMEM);
    cudaFuncSetAttribute(attn2_k, cudaFuncAttributeMaxDynamicSharedMemorySize, A2_SMEM);

    // 1. projections (fp16 tensor cores)
    h16gemm_k<0><<<dim3(HD_ / 128, (B_ * S_) / 128), 256>>>(X, Wq, q, B_ * S_, HD_, C_, nullptr, nullptr);
    h16gemm_k<0><<<dim3(HD_ / 128, (B_ * T_ + 127) / 128), 256>>>(E, Wk, k, B_ * T_, HD_, CE_, nullptr, nullptr);
    h16gemm_k<0><<<dim3(HD_ / 128, (B_ * T_ + 127) / 128), 256>>>(E, Wv, v, B_ * T_, HD_, CE_, nullptr, nullptr);

    // 2. first attention pass (tensor cores) -> normalized probs + token partials
    attn1_k<<<dim3(SCHUNK_, H_, B_), 128, A1_SMEM>>>(q, k, probs, tokpart);
    tok_reduce_k<<<(B_ * T_ + 255) / 256, 256>>>(tokpart, tokscores);
    tok_topk_k<<<B_, 128>>>(tokscores, tokmask);

    // 3. position scores + top-k
    pos_scores_k<<<dim3(S_ / 256, B_), 256>>>(probs, tokmask, posscores);
    pos_topk_k<<<dim3(S_ / 256, B_), 256>>>(posscores, posmask);

    // 4. cross-frame K/V mixing
    kvmix_k<<<(T_ * HD_ + 255) / 256, 256>>>(k, v, tokmask, k2, v2);

    // 5. second attention pass (tensor cores) -> context
    attn2_k<<<dim3(SCHUNK_, H_, B_), 128, A2_SMEM>>>(q, k2, v2, ctx);

    // 6. fused batch-sum + patch correspondence injection
    inject_fused_k<<<(S_ * HD_ / 4 + 255) / 256, 256>>>(ctx, posmask);

    // 7. output projection + bias + residual
    h16gemm_k<1><<<dim3(HD_ / 128, (B_ * S_) / 128), 256>>>(ctx, Wo, out, B_ * S_, HD_, C_, bo, X);
}

// round 8
// speedup vs baseline: 5.8348x; 1.0421x over previous
#include <cuda_runtime.h>
#include <cuda_fp16.h>
#include <math.h>
#include <stdint.h>

#define B_  8
#define S_  4096
#define T_  77
#define TP_ 80            // padded T
#define C_  1280
#define CE_ 2048
#define H_  20
#define D_  64
#define HD_ 1280
#define KTOK_ 12
#define KPOS_ 1229
#define SCHUNK_ (S_/128)   // 32

#define SCALE_ 0.125f
#define STRENGTH_ 0.5f
#define ALPHA_ 0.7f
#define WINJ_ 0.25f        // FIW * STRENGTH

// ---------------- scratch (device globals; no allocations) ----------------
__device__ float g_q[(size_t)B_*S_*HD_];
__device__ float g_k[B_*T_*HD_];
__device__ float g_v[B_*T_*HD_];
__device__ float g_k2[B_*T_*HD_];
__device__ float g_v2[B_*T_*HD_];
__device__ float g_posp[B_*H_*S_];          // per-(b,h,s) pos partials
__device__ float g_tokpart[B_*H_*SCHUNK_*T_];
__device__ float g_tokscores[B_*T_];
__device__ int   g_tokmask[B_*T_];
__device__ float g_posscores[B_*S_];
__device__ int   g_posmask[B_*S_];
__device__ float g_ctx[(size_t)B_*S_*HD_];

// ---------------- mma helpers ----------------
__device__ __forceinline__ void mma_f16(float* c, const uint32_t* a, const uint32_t* b) {
    asm volatile(
        "mma.sync.aligned.m16n8k16.row.col.f32.f16.f16.f32 "
        "{%0,%1,%2,%3},{%4,%5,%6,%7},{%8,%9},{%0,%1,%2,%3};"
        : "+f"(c[0]), "+f"(c[1]), "+f"(c[2]), "+f"(c[3])
        : "r"(a[0]), "r"(a[1]), "r"(a[2]), "r"(a[3]), "r"(b[0]), "r"(b[1]));
}
__device__ __forceinline__ void ldmx4(uint32_t* r, const void* p) {
    uint32_t a = (uint32_t)__cvta_generic_to_shared(p);
    asm volatile("ldmatrix.sync.aligned.m8n8.x4.shared.b16 {%0,%1,%2,%3}, [%4];"
                 : "=r"(r[0]), "=r"(r[1]), "=r"(r[2]), "=r"(r[3]) : "r"(a));
}
__device__ __forceinline__ void ldmx4t(uint32_t* r, const void* p) {
    uint32_t a = (uint32_t)__cvta_generic_to_shared(p);
    asm volatile("ldmatrix.sync.aligned.m8n8.x4.trans.shared.b16 {%0,%1,%2,%3}, [%4];"
                 : "=r"(r[0]), "=r"(r[1]), "=r"(r[2]), "=r"(r[3]) : "r"(a));
}
__device__ __forceinline__ uint32_t pack_h2(float x, float y) {
    __half2 h = __floats2half2_rn(x, y);
    return *(uint32_t*)&h;
}

// ====================================================================
//  fp16 mma.sync GEMM : 128x128x32 tiles, 256 threads, DOUBLE-BUFFERED smem
// ====================================================================
#define AKP_ 40
#define BNP_ 136

template<int EPI>
__global__ __launch_bounds__(256) void h16gemm_k(
    const float* __restrict__ A, const float* __restrict__ Bm, float* __restrict__ Cm,
    int M, int N, int K,
    const float* __restrict__ bias, const float* __restrict__ resid)
{
    __shared__ __half As[2][128][AKP_];
    __shared__ __half Bs[2][32][BNP_];

    const int tid  = threadIdx.x;
    const int wid  = tid >> 5, lane = tid & 31;
    const int wm   = wid & 1;
    const int wn   = wid >> 1;
    const int bm0  = blockIdx.y * 128;
    const int bn0  = blockIdx.x * 128;

    float acc[4][4][4];
#pragma unroll
    for (int i = 0; i < 4; i++)
#pragma unroll
        for (int j = 0; j < 4; j++)
#pragma unroll
            for (int r = 0; r < 4; r++) acc[i][j][r] = 0.f;

    const int ltile = lane >> 3, lrit = lane & 7;
    const int a_m  = wm * 64 + (ltile & 1) * 8 + lrit;
    const int a_kc = (ltile >> 1) * 8;
    const int b_k  = (ltile & 1) * 8 + lrit;
    const int b_n  = wn * 32 + (ltile >> 1) * 8;

    float4 pa[4], pb[4];
#pragma unroll
    for (int i = 0; i < 4; i++) {
        int f = tid + i * 256;
        int row = f >> 3;
        int kc4 = (f & 7) * 4;
        int r = bm0 + row;
        pa[i] = (r < M) ? *(const float4*)(A + (size_t)r * K + kc4)
                        : make_float4(0.f, 0.f, 0.f, 0.f);
        int kr = f >> 5;
        int n4 = (f & 31) * 4;
        pb[i] = *(const float4*)(Bm + (size_t)kr * N + bn0 + n4);
    }
    // prologue: store tile0 into buffer 0
#pragma unroll
    for (int i = 0; i < 4; i++) {
        int f = tid + i * 256;
        int row = f >> 3;
        int kc4 = (f & 7) * 4;
        uint2 av; av.x = pack_h2(pa[i].x, pa[i].y); av.y = pack_h2(pa[i].z, pa[i].w);
        *(uint2*)&As[0][row][kc4] = av;
        int kr = f >> 5;
        int n4 = (f & 31) * 4;
        uint2 bv; bv.x = pack_h2(pb[i].x, pb[i].y); bv.y = pack_h2(pb[i].z, pb[i].w);
        *(uint2*)&Bs[0][kr][n4] = bv;
    }
    __syncthreads();

    int rbuf = 0;
    for (int k0 = 0; k0 < K; k0 += 32) {
        const bool more = (k0 + 32 < K);
        if (more) {
#pragma unroll
            for (int i = 0; i < 4; i++) {
                int f = tid + i * 256;
                int row = f >> 3;
                int kc4 = (f & 7) * 4;
                int r = bm0 + row;
                pa[i] = (r < M) ? *(const float4*)(A + (size_t)r * K + k0 + 32 + kc4)
                                : make_float4(0.f, 0.f, 0.f, 0.f);
                int kr = f >> 5;
                int n4 = (f & 31) * 4;
                pb[i] = *(const float4*)(Bm + (size_t)(k0 + 32 + kr) * N + bn0 + n4);
            }
        }

#pragma unroll
        for (int kk = 0; kk < 32; kk += 16) {
            uint32_t af[4][4], bf[4][2];
#pragma unroll
            for (int mt = 0; mt < 4; mt++)
                ldmx4(af[mt], &As[rbuf][a_m + mt * 16][kk + a_kc]);
#pragma unroll
            for (int p = 0; p < 2; p++) {
                uint32_t br[4];
                ldmx4t(br, &Bs[rbuf][kk + b_k][b_n + p * 16]);
                bf[2 * p][0]     = br[0];
                bf[2 * p][1]     = br[1];
                bf[2 * p + 1][0] = br[2];
                bf[2 * p + 1][1] = br[3];
            }
#pragma unroll
            for (int mt = 0; mt < 4; mt++)
#pragma unroll
                for (int nt = 0; nt < 4; nt++)
                    mma_f16(acc[mt][nt], af[mt], bf[nt]);
        }

        if (more) {
            const int wb = rbuf ^ 1;
#pragma unroll
            for (int i = 0; i < 4; i++) {
                int f = tid + i * 256;
                int row = f >> 3;
                int kc4 = (f & 7) * 4;
                uint2 av; av.x = pack_h2(pa[i].x, pa[i].y); av.y = pack_h2(pa[i].z, pa[i].w);
                *(uint2*)&As[wb][row][kc4] = av;
                int kr = f >> 5;
                int n4 = (f & 31) * 4;
                uint2 bv; bv.x = pack_h2(pb[i].x, pb[i].y); bv.y = pack_h2(pb[i].z, pb[i].w);
                *(uint2*)&Bs[wb][kr][n4] = bv;
            }
            __syncthreads();
        }
        rbuf ^= 1;
    }

    const int row0 = bm0 + wm * 64 + (lane >> 2);
    const int col0 = bn0 + wn * 32 + 2 * (lane & 3);
#pragma unroll
    for (int mt = 0; mt < 4; mt++) {
#pragma unroll
        for (int nt = 0; nt < 4; nt++) {
            int r = row0 + mt * 16;
            int c = col0 + nt * 8;
            float v0 = acc[mt][nt][0], v1 = acc[mt][nt][1];
            float v2 = acc[mt][nt][2], v3 = acc[mt][nt][3];
            if (EPI) {
                float b0v = bias[c], b1v = bias[c + 1];
                if (r < M) {
                    float2 rr = *(const float2*)(resid + (size_t)r * N + c);
                    v0 += b0v + rr.x; v1 += b1v + rr.y;
                }
                if (r + 8 < M) {
                    float2 rr = *(const float2*)(resid + (size_t)(r + 8) * N + c);
                    v2 += b0v + rr.x; v3 += b1v + rr.y;
                }
            }
            if (r < M) { float2 o; o.x = v0; o.y = v1; *(float2*)(Cm + (size_t)r * N + c) = o; }
            if (r + 8 < M) { float2 o; o.x = v2; o.y = v3; *(float2*)(Cm + (size_t)(r + 8) * N + c) = o; }
        }
    }
}

// ====================================================================
//  attention pass 1 : tensor-core logits -> softmax -> tokpart ONLY
// ====================================================================
#define QP_  72   // Q smem pitch (halves)
#define KP2_ 88   // K smem [k][t] pitch (halves)

__global__ __launch_bounds__(128) void attn1_k(
    const float* __restrict__ q, const float* __restrict__ kk,
    float* __restrict__ tokpart)
{
    __shared__ __half Qs[128 * QP_];
    __shared__ __half Ks[64 * KP2_];
    __shared__ float tpw[4][TP_];

    const int b = blockIdx.z, h = blockIdx.y;
    const int tid = threadIdx.x;
    const int wid = tid >> 5, lane = tid & 31;
    const int bm0 = blockIdx.x * 128;

#pragma unroll
    for (int i = 0; i < 16; i++) {
        int f = tid + i * 128;
        int row = f >> 4, c4 = (f & 15) * 4;
        float4 v = *(const float4*)(q + ((size_t)(b * S_) + bm0 + row) * HD_ + h * D_ + c4);
        uint2 av; av.x = pack_h2(v.x, v.y); av.y = pack_h2(v.z, v.w);
        *(uint2*)&Qs[row * QP_ + c4] = av;
    }
    for (int f = tid; f < 64 * KP2_ / 2; f += 128) ((uint32_t*)Ks)[f] = 0;
    __syncthreads();
    for (int f = tid; f < T_ * 16; f += 128) {
        int t = f >> 4, d4 = (f & 15) * 4;
        float4 v = *(const float4*)(kk + ((size_t)(b * T_) + t) * HD_ + h * D_ + d4);
        Ks[(d4 + 0) * KP2_ + t] = __float2half_rn(v.x);
        Ks[(d4 + 1) * KP2_ + t] = __float2half_rn(v.y);
        Ks[(d4 + 2) * KP2_ + t] = __float2half_rn(v.z);
        Ks[(d4 + 3) * KP2_ + t] = __float2half_rn(v.w);
    }
    __syncthreads();

    const int ltile = lane >> 3, lrit = lane & 7;
    const int a_m  = wid * 32 + (ltile & 1) * 8 + lrit;
    const int a_kc = (ltile >> 1) * 8;
    const int b_k  = (ltile & 1) * 8 + lrit;
    const int b_n  = (ltile >> 1) * 8;

    float acc[2][10][4];
#pragma unroll
    for (int mt = 0; mt < 2; mt++)
#pragma unroll
        for (int nt = 0; nt < 10; nt++)
#pragma unroll
            for (int r = 0; r < 4; r++) acc[mt][nt][r] = 0.f;

#pragma unroll
    for (int kkk = 0; kkk < 64; kkk += 16) {
        uint32_t af[2][4], bf[10][2];
#pragma unroll
        for (int mt = 0; mt < 2; mt++)
            ldmx4(af[mt], &Qs[(a_m + mt * 16) * QP_ + kkk + a_kc]);
#pragma unroll
        for (int p = 0; p < 5; p++) {
            uint32_t br[4];
            ldmx4t(br, &Ks[(kkk + b_k) * KP2_ + b_n + p * 16]);
            bf[2 * p][0]     = br[0];
            bf[2 * p][1]     = br[1];
            bf[2 * p + 1][0] = br[2];
            bf[2 * p + 1][1] = br[3];
        }
#pragma unroll
        for (int mt = 0; mt < 2; mt++)
#pragma unroll
            for (int nt = 0; nt < 10; nt++)
                mma_f16(acc[mt][nt], af[mt], bf[nt]);
    }

    float rs_a[2] = {0.f, 0.f}, rs_b[2] = {0.f, 0.f};
#pragma unroll
    for (int mt = 0; mt < 2; mt++) {
#pragma unroll
        for (int nt = 0; nt < 10; nt++) {
            int col = nt * 8 + 2 * (lane & 3);
            float e0 = (col     < T_) ? __expf(acc[mt][nt][0] * SCALE_) : 0.f;
            float e1 = (col + 1 < T_) ? __expf(acc[mt][nt][1] * SCALE_) : 0.f;
            float e2 = (col     < T_) ? __expf(acc[mt][nt][2] * SCALE_) : 0.f;
            float e3 = (col + 1 < T_) ? __expf(acc[mt][nt][3] * SCALE_) : 0.f;
            acc[mt][nt][0] = e0; acc[mt][nt][1] = e1;
            acc[mt][nt][2] = e2; acc[mt][nt][3] = e3;
            rs_a[mt] += e0 + e1;
            rs_b[mt] += e2 + e3;
        }
        rs_a[mt] += __shfl_xor_sync(0xffffffffu, rs_a[mt], 1);
        rs_a[mt] += __shfl_xor_sync(0xffffffffu, rs_a[mt], 2);
        rs_b[mt] += __shfl_xor_sync(0xffffffffu, rs_b[mt], 1);
        rs_b[mt] += __shfl_xor_sync(0xffffffffu, rs_b[mt], 2);
    }
    float inv_a[2] = {1.f / rs_a[0], 1.f / rs_a[1]};
    float inv_b[2] = {1.f / rs_b[0], 1.f / rs_b[1]};

    // per-warp column sums of normalized probs via xor-shuffles (32 rows/warp)
#pragma unroll
    for (int nt = 0; nt < 10; nt++) {
        float cs0 = acc[0][nt][0] * inv_a[0] + acc[0][nt][2] * inv_b[0]
                  + acc[1][nt][0] * inv_a[1] + acc[1][nt][2] * inv_b[1];
        float cs1 = acc[0][nt][1] * inv_a[0] + acc[0][nt][3] * inv_b[0]
                  + acc[1][nt][1] * inv_a[1] + acc[1][nt][3] * inv_b[1];
#pragma unroll
        for (int o = 4; o <= 16; o <<= 1) {
            cs0 += __shfl_xor_sync(0xffffffffu, cs0, o);
            cs1 += __shfl_xor_sync(0xffffffffu, cs1, o);
        }
        if (lane < 4) {
            int col = nt * 8 + 2 * lane;
            tpw[wid][col]     = cs0;
            tpw[wid][col + 1] = cs1;
        }
    }
    __syncthreads();
    if (tid < T_) {
        int lin = (b * H_ + h) * SCHUNK_ + blockIdx.x;
        tokpart[(size_t)lin * T_ + tid] = tpw[0][tid] + tpw[1][tid] + tpw[2][tid] + tpw[3][tid];
    }
}

// ---------------- token score reduce + top-k ----------------
__global__ void tok_reduce_k(const float* __restrict__ tokpart, float* __restrict__ scores)
{
    int idx = blockIdx.x * blockDim.x + threadIdx.x;
    if (idx >= B_ * T_) return;
    int b = idx / T_, t = idx % T_;
    float sum = 0.f;
    for (int h = 0; h < H_; h++)
        for (int c = 0; c < SCHUNK_; c++)
            sum += tokpart[(size_t)((b * H_ + h) * SCHUNK_ + c) * T_ + t];
    scores[idx] = sum * (1.f / (float)(H_ * S_));
}

__global__ void tok_topk_k(const float* __restrict__ scores, int* __restrict__ mask)
{
    int b = blockIdx.x, tid = threadIdx.x;
    __shared__ float sc[T_];
    if (tid < T_) sc[tid] = scores[b * T_ + tid];
    __syncthreads();
    if (tid < T_) {
        float v = sc[tid];
        int rank = 0;
        for (int j = 0; j < T_; j++) {
            float u = sc[j];
            rank += (int)((u > v) || (u == v && j < tid));
        }
        mask[b * T_ + tid] = (rank < KTOK_) ? 1 : 0;
    }
}

// ---------------- pos partial reduce + top-k ----------------
__global__ void pos_reduce_k(const float* __restrict__ posp, float* __restrict__ scores)
{
    int idx = blockIdx.x * blockDim.x + threadIdx.x;
    if (idx >= B_ * S_) return;
    int b = idx / S_, s = idx % S_;
    float sum = 0.f;
#pragma unroll
    for (int h = 0; h < H_; h++) sum += posp[(size_t)(b * H_ + h) * S_ + s];
    scores[idx] = sum * (1.f / (float)H_);
}

__global__ __launch_bounds__(256) void pos_topk_k(const float* __restrict__ scores, int* __restrict__ mask)
{
    const int b = blockIdx.y;
    __shared__ float sc[S_];
    for (int i = threadIdx.x; i < S_; i += 256) sc[i] = scores[b * S_ + i];
    __syncthreads();
    const int i = blockIdx.x * 256 + threadIdx.x;
    float v = sc[i];
    int rank = 0;
    for (int j = 0; j < S_; j++) {
        float u = sc[j];
        rank += (int)((u > v) || (u == v && j < i));
    }
    mask[b * S_ + i] = (rank < KPOS_) ? 1 : 0;
}

// ---------------- cross-frame K/V mixing ----------------
__global__ void kvmix_k(const float* __restrict__ kin, const float* __restrict__ vin,
                        const int* __restrict__ tokmask,
                        float* __restrict__ k2, float* __restrict__ v2)
{
    int idx = blockIdx.x * blockDim.x + threadIdx.x;
    if (idx >= T_ * HD_) return;
    int t = idx / HD_;
    int c = idx % HD_;
    float kv[B_], vv[B_];
    float ksum = 0.f, vsum = 0.f;
#pragma unroll
    for (int b = 0; b < B_; b++) {
        size_t off = ((size_t)(b * T_) + t) * HD_ + c;
        kv[b] = kin[off];
        vv[b] = vin[off];
        ksum += kv[b];
        vsum += vv[b];
    }
#pragma unroll
    for (int b = 0; b < B_; b++) {
        float tm = tokmask[b * T_ + t] ? STRENGTH_ : 0.f;
        size_t off = ((size_t)(b * T_) + t) * HD_ + c;
        float x  = kv[b];
        float mo = (ksum - x) * (1.f / (float)(B_ - 1));
        float mixed = ALPHA_ * x + (1.f - ALPHA_) * mo;
        k2[off] = x + tm * (mixed - x);
        x  = vv[b];
        mo = (vsum - x) * (1.f / (float)(B_ - 1));
        mixed = ALPHA_ * x + (1.f - ALPHA_) * mo;
        v2[off] = x + tm * (mixed - x);
    }
}

// ====================================================================
//  attention pass 2 : QK (pos partials) + QK2 softmax + P·V
// ====================================================================
#define VP_  72
#define PP_  88
#define A2_QS 0
#define A2_KS (A2_QS + 128 * QP_ * 2)           // K  (orig)
#define A2_LS (A2_KS + 64 * KP2_ * 2)           // K2
#define A2_VS (A2_LS + 64 * KP2_ * 2)
#define A2_PS (A2_VS + TP_ * VP_ * 2)
#define A2_MS (A2_PS + 128 * PP_ * 2)           // mask floats
#define A2_SMEM (A2_MS + TP_ * 4)

__global__ __launch_bounds__(128) void attn2_k(
    const float* __restrict__ q, const float* __restrict__ kk,
    const float* __restrict__ k2, const float* __restrict__ v2,
    const int* __restrict__ tokmask,
    float* __restrict__ posp, float* __restrict__ ctx)
{
    extern __shared__ char dsm[];
    __half* Qs = (__half*)(dsm + A2_QS);
    __half* Ks = (__half*)(dsm + A2_KS);
    __half* Ls = (__half*)(dsm + A2_LS);
    __half* Vs = (__half*)(dsm + A2_VS);
    __half* Ph = (__half*)(dsm + A2_PS);
    float*  Ms = (float*)(dsm + A2_MS);

    const int b = blockIdx.z, h = blockIdx.y;
    const int tid = threadIdx.x;
    const int wid = tid >> 5, lane = tid & 31;
    const int bm0 = blockIdx.x * 128;

#pragma unroll
    for (int i = 0; i < 16; i++) {
        int f = tid + i * 128;
        int row = f >> 4, c4 = (f & 15) * 4;
        float4 v = *(const float4*)(q + ((size_t)(b * S_) + bm0 + row) * HD_ + h * D_ + c4);
        uint2 av; av.x = pack_h2(v.x, v.y); av.y = pack_h2(v.z, v.w);
        *(uint2*)&Qs[row * QP_ + c4] = av;
    }
    for (int f = tid; f < 64 * KP2_ / 2; f += 128) { ((uint32_t*)Ks)[f] = 0; ((uint32_t*)Ls)[f] = 0; }
    for (int f = tid; f < TP_ * VP_ / 2; f += 128) ((uint32_t*)Vs)[f] = 0;
    if (tid < TP_) Ms[tid] = (tid < T_) ? (float)tokmask[b * T_ + tid] : 0.f;
    __syncthreads();
    for (int f = tid; f < T_ * 16; f += 128) {
        int t = f >> 4, d4 = (f & 15) * 4;
        float4 kv = *(const float4*)(kk + ((size_t)(b * T_) + t) * HD_ + h * D_ + d4);
        Ks[(d4 + 0) * KP2_ + t] = __float2half_rn(kv.x);
        Ks[(d4 + 1) * KP2_ + t] = __float2half_rn(kv.y);
        Ks[(d4 + 2) * KP2_ + t] = __float2half_rn(kv.z);
        Ks[(d4 + 3) * KP2_ + t] = __float2half_rn(kv.w);
        float4 lv = *(const float4*)(k2 + ((size_t)(b * T_) + t) * HD_ + h * D_ + d4);
        Ls[(d4 + 0) * KP2_ + t] = __float2half_rn(lv.x);
        Ls[(d4 + 1) * KP2_ + t] = __float2half_rn(lv.y);
        Ls[(d4 + 2) * KP2_ + t] = __float2half_rn(lv.z);
        Ls[(d4 + 3) * KP2_ + t] = __float2half_rn(lv.w);
        float4 vv = *(const float4*)(v2 + ((size_t)(b * T_) + t) * HD_ + h * D_ + d4);
        uint2 av; av.x = pack_h2(vv.x, vv.y); av.y = pack_h2(vv.z, vv.w);
        *(uint2*)&Vs[t * VP_ + d4] = av;
    }
    __syncthreads();

    const int ltile = lane >> 3, lrit = lane & 7;
    const int a_m  = wid * 32 + (ltile & 1) * 8 + lrit;
    const int a_kc = (ltile >> 1) * 8;
    const int b_k  = (ltile & 1) * 8 + lrit;
    const int b_n  = (ltile >> 1) * 8;

    // ---- pass A: logits = Q K^T (original K) -> pos partials ----
    {
        float acc[2][10][4];
#pragma unroll
        for (int mt = 0; mt < 2; mt++)
#pragma unroll
            for (int nt = 0; nt < 10; nt++)
#pragma unroll
                for (int r = 0; r < 4; r++) acc[mt][nt][r] = 0.f;

#pragma unroll
        for (int kkk = 0; kkk < 64; kkk += 16) {
            uint32_t af[2][4], bf[10][2];
#pragma unroll
            for (int mt = 0; mt < 2; mt++)
                ldmx4(af[mt], &Qs[(a_m + mt * 16) * QP_ + kkk + a_kc]);
#pragma unroll
            for (int p = 0; p < 5; p++) {
                uint32_t br[4];
                ldmx4t(br, &Ks[(kkk + b_k) * KP2_ + b_n + p * 16]);
                bf[2 * p][0]     = br[0];
                bf[2 * p][1]     = br[1];
                bf[2 * p + 1][0] = br[2];
                bf[2 * p + 1][1] = br[3];
            }
#pragma unroll
            for (int mt = 0; mt < 2; mt++)
#pragma unroll
                for (int nt = 0; nt < 10; nt++)
                    mma_f16(acc[mt][nt], af[mt], bf[nt]);
        }

        float rs_a[2] = {0.f, 0.f}, rs_b[2] = {0.f, 0.f};
        float ms_a[2] = {0.f, 0.f}, ms_b[2] = {0.f, 0.f};
#pragma unroll
        for (int mt = 0; mt < 2; mt++) {
#pragma unroll
            for (int nt = 0; nt < 10; nt++) {
                int col = nt * 8 + 2 * (lane & 3);
                float m0 = Ms[col], m1 = Ms[col + 1];
                float e0 = (col     < T_) ? __expf(acc[mt][nt][0] * SCALE_) : 0.f;
                float e1 = (col + 1 < T_) ? __expf(acc[mt][nt][1] * SCALE_) : 0.f;
                float e2 = (col     < T_) ? __expf(acc[mt][nt][2] * SCALE_) : 0.f;
                float e3 = (col + 1 < T_) ? __expf(acc[mt][nt][3] * SCALE_) : 0.f;
                rs_a[mt] += e0 + e1;
                rs_b[mt] += e2 + e3;
                ms_a[mt] += e0 * m0 + e1 * m1;
                ms_b[mt] += e2 * m0 + e3 * m1;
            }
            rs_a[mt] += __shfl_xor_sync(0xffffffffu, rs_a[mt], 1);
            rs_a[mt] += __shfl_xor_sync(0xffffffffu, rs_a[mt], 2);
            rs_b[mt] += __shfl_xor_sync(0xffffffffu, rs_b[mt], 1);
            rs_b[mt] += __shfl_xor_sync(0xffffffffu, rs_b[mt], 2);
            ms_a[mt] += __shfl_xor_sync(0xffffffffu, ms_a[mt], 1);
            ms_a[mt] += __shfl_xor_sync(0xffffffffu, ms_a[mt], 2);
            ms_b[mt] += __shfl_xor_sync(0xffffffffu, ms_b[mt], 1);
            ms_b[mt] += __shfl_xor_sync(0xffffffffu, ms_b[mt], 2);
        }
        if ((lane & 3) == 0) {
            const size_t pb2 = (size_t)(b * H_ + h) * S_ + bm0;
#pragma unroll
            for (int mt = 0; mt < 2; mt++) {
                int r = wid * 32 + mt * 16 + (lane >> 2);
                posp[pb2 + r]     = ms_a[mt] / rs_a[mt];
                posp[pb2 + r + 8] = ms_b[mt] / rs_b[mt];
            }
        }
    }

    // ---- pass B: logits2 = Q K2^T -> softmax -> P fp16 -> P V ----
    float acc[2][10][4];
#pragma unroll
    for (int mt = 0; mt < 2; mt++)
#pragma unroll
        for (int nt = 0; nt < 10; nt++)
#pragma unroll
            for (int r = 0; r < 4; r++) acc[mt][nt][r] = 0.f;

#pragma unroll
    for (int kkk = 0; kkk < 64; kkk += 16) {
        uint32_t af[2][4], bf[10][2];
#pragma unroll
        for (int mt = 0; mt < 2; mt++)
            ldmx4(af[mt], &Qs[(a_m + mt * 16) * QP_ + kkk + a_kc]);
#pragma unroll
        for (int p = 0; p < 5; p++) {
            uint32_t br[4];
            ldmx4t(br, &Ls[(kkk + b_k) * KP2_ + b_n + p * 16]);
            bf[2 * p][0]     = br[0];
            bf[2 * p][1]     = br[1];
            bf[2 * p + 1][0] = br[2];
            bf[2 * p + 1][1] = br[3];
        }
#pragma unroll
        for (int mt = 0; mt < 2; mt++)
#pragma unroll
            for (int nt = 0; nt < 10; nt++)
                mma_f16(acc[mt][nt], af[mt], bf[nt]);
    }

    float rs_a[2] = {0.f, 0.f}, rs_b[2] = {0.f, 0.f};
#pragma unroll
    for (int mt = 0; mt < 2; mt++) {
#pragma unroll
        for (int nt = 0; nt < 10; nt++) {
            int col = nt * 8 + 2 * (lane & 3);
            float e0 = (col     < T_) ? __expf(acc[mt][nt][0] * SCALE_) : 0.f;
            float e1 = (col + 1 < T_) ? __expf(acc[mt][nt][1] * SCALE_) : 0.f;
            float e2 = (col     < T_) ? __expf(acc[mt][nt][2] * SCALE_) : 0.f;
            float e3 = (col + 1 < T_) ? __expf(acc[mt][nt][3] * SCALE_) : 0.f;
            acc[mt][nt][0] = e0; acc[mt][nt][1] = e1;
            acc[mt][nt][2] = e2; acc[mt][nt][3] = e3;
            rs_a[mt] += e0 + e1;
            rs_b[mt] += e2 + e3;
        }
        rs_a[mt] += __shfl_xor_sync(0xffffffffu, rs_a[mt], 1);
        rs_a[mt] += __shfl_xor_sync(0xffffffffu, rs_a[mt], 2);
        rs_b[mt] += __shfl_xor_sync(0xffffffffu, rs_b[mt], 1);
        rs_b[mt] += __shfl_xor_sync(0xffffffffu, rs_b[mt], 2);
    }
    float inv_a[2] = {1.f / rs_a[0], 1.f / rs_a[1]};
    float inv_b[2] = {1.f / rs_b[0], 1.f / rs_b[1]};

#pragma unroll
    for (int mt = 0; mt < 2; mt++) {
        int r = wid * 32 + mt * 16 + (lane >> 2);
#pragma unroll
        for (int nt = 0; nt < 10; nt++) {
            int col = nt * 8 + 2 * (lane & 3);
            *(uint32_t*)&Ph[r * PP_ + col] =
                pack_h2(acc[mt][nt][0] * inv_a[mt], acc[mt][nt][1] * inv_a[mt]);
            *(uint32_t*)&Ph[(r + 8) * PP_ + col] =
                pack_h2(acc[mt][nt][2] * inv_b[mt], acc[mt][nt][3] * inv_b[mt]);
        }
    }
    __syncthreads();

    float acc2[2][8][4];
#pragma unroll
    for (int mt = 0; mt < 2; mt++)
#pragma unroll
        for (int nt = 0; nt < 8; nt++)
#pragma unroll
            for (int r = 0; r < 4; r++) acc2[mt][nt][r] = 0.f;

#pragma unroll
    for (int kkk = 0; kkk < TP_; kkk += 16) {
        uint32_t af[2][4], bf[8][2];
#pragma unroll
        for (int mt = 0; mt < 2; mt++)
            ldmx4(af[mt], &Ph[(a_m + mt * 16) * PP_ + kkk + a_kc]);
#pragma unroll
        for (int p = 0; p < 4; p++) {
            uint32_t br[4];
            ldmx4t(br, &Vs[(kkk + b_k) * VP_ + b_n + p * 16]);
            bf[2 * p][0]     = br[0];
            bf[2 * p][1]     = br[1];
            bf[2 * p + 1][0] = br[2];
            bf[2 * p + 1][1] = br[3];
        }
#pragma unroll
        for (int mt = 0; mt < 2; mt++)
#pragma unroll
            for (int nt = 0; nt < 8; nt++)
                mma_f16(acc2[mt][nt], af[mt], bf[nt]);
    }

#pragma unroll
    for (int mt = 0; mt < 2; mt++) {
        int r = wid * 32 + mt * 16 + (lane >> 2);
#pragma unroll
        for (int nt = 0; nt < 8; nt++) {
            int col = nt * 8 + 2 * (lane & 3);
            float2 oA; oA.x = acc2[mt][nt][0]; oA.y = acc2[mt][nt][1];
            float2 oB; oB.x = acc2[mt][nt][2]; oB.y = acc2[mt][nt][3];
            *(float2*)(ctx + ((size_t)(b * S_) + bm0 + r) * HD_ + h * D_ + col)     = oA;
            *(float2*)(ctx + ((size_t)(b * S_) + bm0 + r + 8) * HD_ + h * D_ + col) = oB;
        }
    }
}

// ---------------- fused context batch-sum + patch injection ----------------
__global__ __launch_bounds__(256) void inject_fused_k(
    float* __restrict__ ctx, const int* __restrict__ posmask)
{
    const int i4 = blockIdx.x * 256 + threadIdx.x;
    if (i4 >= S_ * HD_ / 4) return;
    const size_t base = (size_t)i4 * 4;
    const int s = (int)(base / HD_);

    float4 v[B_];
    float4 sum = make_float4(0.f, 0.f, 0.f, 0.f);
#pragma unroll
    for (int b = 0; b < B_; b++) {
        v[b] = *(const float4*)(ctx + (size_t)b * S_ * HD_ + base);
        sum.x += v[b].x; sum.y += v[b].y; sum.z += v[b].z; sum.w += v[b].w;
    }
#pragma unroll
    for (int b = 0; b < B_; b++) {
        if (posmask[b * S_ + s]) {
            const float c7 = 1.f / (float)(B_ - 1);
            float4 o;
            o.x = v[b].x + WINJ_ * ((sum.x - v[b].x) * c7 - v[b].x);
            o.y = v[b].y + WINJ_ * ((sum.y - v[b].y) * c7 - v[b].y);
            o.z = v[b].z + WINJ_ * ((sum.z - v[b].z) * c7 - v[b].z);
            o.w = v[b].w + WINJ_ * ((sum.w - v[b].w) * c7 - v[b].w);
            *(float4*)(ctx + (size_t)b * S_ * HD_ + base) = o;
        }
    }
}

// ---------------- launch ----------------
extern "C" void kernel_launch(void* const* d_in, const int* in_sizes, int n_in,
                              void* d_out, int out_size)
{
    (void)in_sizes; (void)n_in; (void)out_size;
    const float* X  = (const float*)d_in[0];
    const float* E  = (const float*)d_in[1];
    const float* Wq = (const float*)d_in[2];
    const float* Wk = (const float*)d_in[3];
    const float* Wv = (const float*)d_in[4];
    const float* Wo = (const float*)d_in[5];
    const float* bo = (const float*)d_in[6];
    float* out = (float*)d_out;

    float *q, *k, *v, *k2, *v2, *posp, *tokpart, *tokscores, *posscores, *ctx;
    int *tokmask, *posmask;
    cudaGetSymbolAddress((void**)&q,        g_q);
    cudaGetSymbolAddress((void**)&k,        g_k);
    cudaGetSymbolAddress((void**)&v,        g_v);
    cudaGetSymbolAddress((void**)&k2,       g_k2);
    cudaGetSymbolAddress((void**)&v2,       g_v2);
    cudaGetSymbolAddress((void**)&posp,     g_posp);
    cudaGetSymbolAddress((void**)&tokpart,  g_tokpart);
    cudaGetSymbolAddress((void**)&tokscores,g_tokscores);
    cudaGetSymbolAddress((void**)&tokmask,  g_tokmask);
    cudaGetSymbolAddress((void**)&posscores,g_posscores);
    cudaGetSymbolAddress((void**)&posmask,  g_posmask);
    cudaGetSymbolAddress((void**)&ctx,      g_ctx);

    cudaFuncSetAttribute(attn2_k, cudaFuncAttributeMaxDynamicSharedMemorySize, A2_SMEM);

    // 1. projections (fp16 tensor cores, double-buffered)
    h16gemm_k<0><<<dim3(HD_ / 128, (B_ * S_) / 128), 256>>>(X, Wq, q, B_ * S_, HD_, C_, nullptr, nullptr);
    h16gemm_k<0><<<dim3(HD_ / 128, (B_ * T_ + 127) / 128), 256>>>(E, Wk, k, B_ * T_, HD_, CE_, nullptr, nullptr);
    h16gemm_k<0><<<dim3(HD_ / 128, (B_ * T_ + 127) / 128), 256>>>(E, Wv, v, B_ * T_, HD_, CE_, nullptr, nullptr);

    // 2. first attention pass -> token partials only
    attn1_k<<<dim3(SCHUNK_, H_, B_), 128>>>(q, k, tokpart);
    tok_reduce_k<<<(B_ * T_ + 255) / 256, 256>>>(tokpart, tokscores);
    tok_topk_k<<<B_, 128>>>(tokscores, tokmask);

    // 3. cross-frame K/V mixing
    kvmix_k<<<(T_ * HD_ + 255) / 256, 256>>>(k, v, tokmask, k2, v2);

    // 4. second attention pass -> pos partials + context
    attn2_k<<<dim3(SCHUNK_, H_, B_), 128, A2_SMEM>>>(q, k, k2, v2, tokmask, posp, ctx);

    // 5. position scores + top-k
    pos_reduce_k<<<(B_ * S_ + 255) / 256, 256>>>(posp, posscores);
    pos_topk_k<<<dim3(S_ / 256, B_), 256>>>(posscores, posmask);

    // 6. fused batch-sum + patch correspondence injection
    inject_fused_k<<<(S_ * HD_ / 4 + 255) / 256, 256>>>(ctx, posmask);

    // 7. output projection + bias + residual
    h16gemm_k<1><<<dim3(HD_ / 128, (B_ * S_) / 128), 256>>>(ctx, Wo, out, B_ * S_, HD_, C_, bo, X);
}

// round 9
// speedup vs baseline: 6.0840x; 1.0427x over previous
#include <cuda_runtime.h>
#include <cuda_fp16.h>
#include <math.h>
#include <stdint.h>

#define B_  8
#define S_  4096
#define T_  77
#define TP_ 80            // padded T
#define C_  1280
#define CE_ 2048
#define H_  20
#define D_  64
#define HD_ 1280
#define KTOK_ 12
#define KPOS_ 1229
#define SCHUNK_ (S_/128)   // 32

#define SCALE_ 0.125f
#define STRENGTH_ 0.5f
#define ALPHA_ 0.7f
#define WINJ_ 0.25f        // FIW * STRENGTH

// ---------------- scratch (device globals; no allocations) ----------------
__device__ __half g_q[(size_t)B_*S_*HD_];    // fp16 Q
__device__ float g_k[B_*T_*HD_];
__device__ float g_v[B_*T_*HD_];
__device__ float g_k2[B_*T_*HD_];
__device__ float g_v2[B_*T_*HD_];
__device__ float g_posp[B_*H_*S_];
__device__ float g_tokpart[B_*H_*SCHUNK_*T_];
__device__ float g_tokscores[B_*T_];
__device__ int   g_tokmask[B_*T_];
__device__ float g_posscores[B_*S_];
__device__ int   g_posmask[B_*S_];
__device__ __half g_ctx[(size_t)B_*S_*HD_];  // fp16 ctx

// ---------------- mma helpers ----------------
__device__ __forceinline__ void mma_f16(float* c, const uint32_t* a, const uint32_t* b) {
    asm volatile(
        "mma.sync.aligned.m16n8k16.row.col.f32.f16.f16.f32 "
        "{%0,%1,%2,%3},{%4,%5,%6,%7},{%8,%9},{%0,%1,%2,%3};"
        : "+f"(c[0]), "+f"(c[1]), "+f"(c[2]), "+f"(c[3])
        : "r"(a[0]), "r"(a[1]), "r"(a[2]), "r"(a[3]), "r"(b[0]), "r"(b[1]));
}
__device__ __forceinline__ void ldmx4(uint32_t* r, const void* p) {
    uint32_t a = (uint32_t)__cvta_generic_to_shared(p);
    asm volatile("ldmatrix.sync.aligned.m8n8.x4.shared.b16 {%0,%1,%2,%3}, [%4];"
                 : "=r"(r[0]), "=r"(r[1]), "=r"(r[2]), "=r"(r[3]) : "r"(a));
}
__device__ __forceinline__ void ldmx4t(uint32_t* r, const void* p) {
    uint32_t a = (uint32_t)__cvta_generic_to_shared(p);
    asm volatile("ldmatrix.sync.aligned.m8n8.x4.trans.shared.b16 {%0,%1,%2,%3}, [%4];"
                 : "=r"(r[0]), "=r"(r[1]), "=r"(r[2]), "=r"(r[3]) : "r"(a));
}
__device__ __forceinline__ uint32_t pack_h2(float x, float y) {
    __half2 h = __floats2half2_rn(x, y);
    return *(uint32_t*)&h;
}

// ====================================================================
//  fp16 mma.sync GEMM : fp32 inputs, double-buffered. OUT16 -> fp16 C.
// ====================================================================
#define AKP_ 40
#define BNP_ 136

template<int OUT16>
__global__ __launch_bounds__(256) void h16gemm_k(
    const float* __restrict__ A, const float* __restrict__ Bm, void* __restrict__ Cm,
    int M, int N, int K)
{
    __shared__ __half As[2][128][AKP_];
    __shared__ __half Bs[2][32][BNP_];

    const int tid  = threadIdx.x;
    const int wid  = tid >> 5, lane = tid & 31;
    const int wm   = wid & 1;
    const int wn   = wid >> 1;
    const int bm0  = blockIdx.y * 128;
    const int bn0  = blockIdx.x * 128;

    float acc[4][4][4];
#pragma unroll
    for (int i = 0; i < 4; i++)
#pragma unroll
        for (int j = 0; j < 4; j++)
#pragma unroll
            for (int r = 0; r < 4; r++) acc[i][j][r] = 0.f;

    const int ltile = lane >> 3, lrit = lane & 7;
    const int a_m  = wm * 64 + (ltile & 1) * 8 + lrit;
    const int a_kc = (ltile >> 1) * 8;
    const int b_k  = (ltile & 1) * 8 + lrit;
    const int b_n  = wn * 32 + (ltile >> 1) * 8;

    float4 pa[4], pb[4];
#pragma unroll
    for (int i = 0; i < 4; i++) {
        int f = tid + i * 256;
        int row = f >> 3;
        int kc4 = (f & 7) * 4;
        int r = bm0 + row;
        pa[i] = (r < M) ? *(const float4*)(A + (size_t)r * K + kc4)
                        : make_float4(0.f, 0.f, 0.f, 0.f);
        int kr = f >> 5;
        int n4 = (f & 31) * 4;
        pb[i] = *(const float4*)(Bm + (size_t)kr * N + bn0 + n4);
    }
#pragma unroll
    for (int i = 0; i < 4; i++) {
        int f = tid + i * 256;
        int row = f >> 3;
        int kc4 = (f & 7) * 4;
        uint2 av; av.x = pack_h2(pa[i].x, pa[i].y); av.y = pack_h2(pa[i].z, pa[i].w);
        *(uint2*)&As[0][row][kc4] = av;
        int kr = f >> 5;
        int n4 = (f & 31) * 4;
        uint2 bv; bv.x = pack_h2(pb[i].x, pb[i].y); bv.y = pack_h2(pb[i].z, pb[i].w);
        *(uint2*)&Bs[0][kr][n4] = bv;
    }
    __syncthreads();

    int rbuf = 0;
    for (int k0 = 0; k0 < K; k0 += 32) {
        const bool more = (k0 + 32 < K);
        if (more) {
#pragma unroll
            for (int i = 0; i < 4; i++) {
                int f = tid + i * 256;
                int row = f >> 3;
                int kc4 = (f & 7) * 4;
                int r = bm0 + row;
                pa[i] = (r < M) ? *(const float4*)(A + (size_t)r * K + k0 + 32 + kc4)
                                : make_float4(0.f, 0.f, 0.f, 0.f);
                int kr = f >> 5;
                int n4 = (f & 31) * 4;
                pb[i] = *(const float4*)(Bm + (size_t)(k0 + 32 + kr) * N + bn0 + n4);
            }
        }

#pragma unroll
        for (int kk = 0; kk < 32; kk += 16) {
            uint32_t af[4][4], bf[4][2];
#pragma unroll
            for (int mt = 0; mt < 4; mt++)
                ldmx4(af[mt], &As[rbuf][a_m + mt * 16][kk + a_kc]);
#pragma unroll
            for (int p = 0; p < 2; p++) {
                uint32_t br[4];
                ldmx4t(br, &Bs[rbuf][kk + b_k][b_n + p * 16]);
                bf[2 * p][0]     = br[0];
                bf[2 * p][1]     = br[1];
                bf[2 * p + 1][0] = br[2];
                bf[2 * p + 1][1] = br[3];
            }
#pragma unroll
            for (int mt = 0; mt < 4; mt++)
#pragma unroll
                for (int nt = 0; nt < 4; nt++)
                    mma_f16(acc[mt][nt], af[mt], bf[nt]);
        }

        if (more) {
            const int wb = rbuf ^ 1;
#pragma unroll
            for (int i = 0; i < 4; i++) {
                int f = tid + i * 256;
                int row = f >> 3;
                int kc4 = (f & 7) * 4;
                uint2 av; av.x = pack_h2(pa[i].x, pa[i].y); av.y = pack_h2(pa[i].z, pa[i].w);
                *(uint2*)&As[wb][row][kc4] = av;
                int kr = f >> 5;
                int n4 = (f & 31) * 4;
                uint2 bv; bv.x = pack_h2(pb[i].x, pb[i].y); bv.y = pack_h2(pb[i].z, pb[i].w);
                *(uint2*)&Bs[wb][kr][n4] = bv;
            }
            __syncthreads();
        }
        rbuf ^= 1;
    }

    const int row0 = bm0 + wm * 64 + (lane >> 2);
    const int col0 = bn0 + wn * 32 + 2 * (lane & 3);
#pragma unroll
    for (int mt = 0; mt < 4; mt++) {
#pragma unroll
        for (int nt = 0; nt < 4; nt++) {
            int r = row0 + mt * 16;
            int c = col0 + nt * 8;
            if (OUT16) {
                if (r < M)
                    *(uint32_t*)((__half*)Cm + (size_t)r * N + c) = pack_h2(acc[mt][nt][0], acc[mt][nt][1]);
                if (r + 8 < M)
                    *(uint32_t*)((__half*)Cm + (size_t)(r + 8) * N + c) = pack_h2(acc[mt][nt][2], acc[mt][nt][3]);
            } else {
                if (r < M) { float2 o; o.x = acc[mt][nt][0]; o.y = acc[mt][nt][1]; *(float2*)((float*)Cm + (size_t)r * N + c) = o; }
                if (r + 8 < M) { float2 o; o.x = acc[mt][nt][2]; o.y = acc[mt][nt][3]; *(float2*)((float*)Cm + (size_t)(r + 8) * N + c) = o; }
            }
        }
    }
}

// ====================================================================
//  fp16-A GEMM (for ctx @ Wo): A fp16, B fp32, epilogue bias+resid, fp32 out
// ====================================================================
__global__ __launch_bounds__(256) void h16gemmA16_k(
    const __half* __restrict__ A, const float* __restrict__ Bm, float* __restrict__ Cm,
    int M, int N, int K,
    const float* __restrict__ bias, const float* __restrict__ resid)
{
    __shared__ __half As[2][128][AKP_];
    __shared__ __half Bs[2][32][BNP_];

    const int tid  = threadIdx.x;
    const int wid  = tid >> 5, lane = tid & 31;
    const int wm   = wid & 1;
    const int wn   = wid >> 1;
    const int bm0  = blockIdx.y * 128;
    const int bn0  = blockIdx.x * 128;

    float acc[4][4][4];
#pragma unroll
    for (int i = 0; i < 4; i++)
#pragma unroll
        for (int j = 0; j < 4; j++)
#pragma unroll
            for (int r = 0; r < 4; r++) acc[i][j][r] = 0.f;

    const int ltile = lane >> 3, lrit = lane & 7;
    const int a_m  = wm * 64 + (ltile & 1) * 8 + lrit;
    const int a_kc = (ltile >> 1) * 8;
    const int b_k  = (ltile & 1) * 8 + lrit;
    const int b_n  = wn * 32 + (ltile >> 1) * 8;

    uint4 pa[2];
    float4 pb[4];
#pragma unroll
    for (int i = 0; i < 2; i++) {
        int f = tid * 2 + i;
        int row = f >> 2;
        int kc8 = (f & 3) * 8;
        pa[i] = *(const uint4*)(A + (size_t)(bm0 + row) * K + kc8);
    }
#pragma unroll
    for (int i = 0; i < 4; i++) {
        int f = tid + i * 256;
        int kr = f >> 5;
        int n4 = (f & 31) * 4;
        pb[i] = *(const float4*)(Bm + (size_t)kr * N + bn0 + n4);
    }
#pragma unroll
    for (int i = 0; i < 2; i++) {
        int f = tid * 2 + i;
        int row = f >> 2;
        int kc8 = (f & 3) * 8;
        *(uint4*)&As[0][row][kc8] = pa[i];
    }
#pragma unroll
    for (int i = 0; i < 4; i++) {
        int f = tid + i * 256;
        int kr = f >> 5;
        int n4 = (f & 31) * 4;
        uint2 bv; bv.x = pack_h2(pb[i].x, pb[i].y); bv.y = pack_h2(pb[i].z, pb[i].w);
        *(uint2*)&Bs[0][kr][n4] = bv;
    }
    __syncthreads();

    int rbuf = 0;
    for (int k0 = 0; k0 < K; k0 += 32) {
        const bool more = (k0 + 32 < K);
        if (more) {
#pragma unroll
            for (int i = 0; i < 2; i++) {
                int f = tid * 2 + i;
                int row = f >> 2;
                int kc8 = (f & 3) * 8;
                pa[i] = *(const uint4*)(A + (size_t)(bm0 + row) * K + k0 + 32 + kc8);
            }
#pragma unroll
            for (int i = 0; i < 4; i++) {
                int f = tid + i * 256;
                int kr = f >> 5;
                int n4 = (f & 31) * 4;
                pb[i] = *(const float4*)(Bm + (size_t)(k0 + 32 + kr) * N + bn0 + n4);
            }
        }

#pragma unroll
        for (int kk = 0; kk < 32; kk += 16) {
            uint32_t af[4][4], bf[4][2];
#pragma unroll
            for (int mt = 0; mt < 4; mt++)
                ldmx4(af[mt], &As[rbuf][a_m + mt * 16][kk + a_kc]);
#pragma unroll
            for (int p = 0; p < 2; p++) {
                uint32_t br[4];
                ldmx4t(br, &Bs[rbuf][kk + b_k][b_n + p * 16]);
                bf[2 * p][0]     = br[0];
                bf[2 * p][1]     = br[1];
                bf[2 * p + 1][0] = br[2];
                bf[2 * p + 1][1] = br[3];
            }
#pragma unroll
            for (int mt = 0; mt < 4; mt++)
#pragma unroll
                for (int nt = 0; nt < 4; nt++)
                    mma_f16(acc[mt][nt], af[mt], bf[nt]);
        }

        if (more) {
            const int wb = rbuf ^ 1;
#pragma unroll
            for (int i = 0; i < 2; i++) {
                int f = tid * 2 + i;
                int row = f >> 2;
                int kc8 = (f & 3) * 8;
                *(uint4*)&As[wb][row][kc8] = pa[i];
            }
#pragma unroll
            for (int i = 0; i < 4; i++) {
                int f = tid + i * 256;
                int kr = f >> 5;
                int n4 = (f & 31) * 4;
                uint2 bv; bv.x = pack_h2(pb[i].x, pb[i].y); bv.y = pack_h2(pb[i].z, pb[i].w);
                *(uint2*)&Bs[wb][kr][n4] = bv;
            }
            __syncthreads();
        }
        rbuf ^= 1;
    }

    const int row0 = bm0 + wm * 64 + (lane >> 2);
    const int col0 = bn0 + wn * 32 + 2 * (lane & 3);
#pragma unroll
    for (int mt = 0; mt < 4; mt++) {
#pragma unroll
        for (int nt = 0; nt < 4; nt++) {
            int r = row0 + mt * 16;
            int c = col0 + nt * 8;
            float b0v = bias[c], b1v = bias[c + 1];
            float2 r0 = *(const float2*)(resid + (size_t)r * N + c);
            float2 r1 = *(const float2*)(resid + (size_t)(r + 8) * N + c);
            float2 o0; o0.x = acc[mt][nt][0] + b0v + r0.x; o0.y = acc[mt][nt][1] + b1v + r0.y;
            float2 o1; o1.x = acc[mt][nt][2] + b0v + r1.x; o1.y = acc[mt][nt][3] + b1v + r1.y;
            *(float2*)(Cm + (size_t)r * N + c) = o0;
            *(float2*)(Cm + (size_t)(r + 8) * N + c) = o1;
        }
    }
}

// ====================================================================
//  attention pass 1 : tensor-core logits -> softmax -> tokpart ONLY
// ====================================================================
#define QP_  72
#define KP2_ 88

__global__ __launch_bounds__(128) void attn1_k(
    const __half* __restrict__ q, const float* __restrict__ kk,
    float* __restrict__ tokpart)
{
    __shared__ __half Qs[128 * QP_];
    __shared__ __half Ks[64 * KP2_];
    __shared__ float tpw[4][TP_];

    const int b = blockIdx.z, h = blockIdx.y;
    const int tid = threadIdx.x;
    const int wid = tid >> 5, lane = tid & 31;
    const int bm0 = blockIdx.x * 128;

#pragma unroll
    for (int i = 0; i < 8; i++) {
        int f = tid + i * 128;
        int row = f >> 3, c8 = (f & 7) * 8;
        uint4 v = *(const uint4*)(q + ((size_t)(b * S_) + bm0 + row) * HD_ + h * D_ + c8);
        *(uint4*)&Qs[row * QP_ + c8] = v;
    }
    for (int f = tid; f < 64 * KP2_ / 2; f += 128) ((uint32_t*)Ks)[f] = 0;
    __syncthreads();
    for (int f = tid; f < T_ * 16; f += 128) {
        int t = f >> 4, d4 = (f & 15) * 4;
        float4 v = *(const float4*)(kk + ((size_t)(b * T_) + t) * HD_ + h * D_ + d4);
        Ks[(d4 + 0) * KP2_ + t] = __float2half_rn(v.x);
        Ks[(d4 + 1) * KP2_ + t] = __float2half_rn(v.y);
        Ks[(d4 + 2) * KP2_ + t] = __float2half_rn(v.z);
        Ks[(d4 + 3) * KP2_ + t] = __float2half_rn(v.w);
    }
    __syncthreads();

    const int ltile = lane >> 3, lrit = lane & 7;
    const int a_m  = wid * 32 + (ltile & 1) * 8 + lrit;
    const int a_kc = (ltile >> 1) * 8;
    const int b_k  = (ltile & 1) * 8 + lrit;
    const int b_n  = (ltile >> 1) * 8;

    float acc[2][10][4];
#pragma unroll
    for (int mt = 0; mt < 2; mt++)
#pragma unroll
        for (int nt = 0; nt < 10; nt++)
#pragma unroll
            for (int r = 0; r < 4; r++) acc[mt][nt][r] = 0.f;

#pragma unroll
    for (int kkk = 0; kkk < 64; kkk += 16) {
        uint32_t af[2][4], bf[10][2];
#pragma unroll
        for (int mt = 0; mt < 2; mt++)
            ldmx4(af[mt], &Qs[(a_m + mt * 16) * QP_ + kkk + a_kc]);
#pragma unroll
        for (int p = 0; p < 5; p++) {
            uint32_t br[4];
            ldmx4t(br, &Ks[(kkk + b_k) * KP2_ + b_n + p * 16]);
            bf[2 * p][0]     = br[0];
            bf[2 * p][1]     = br[1];
            bf[2 * p + 1][0] = br[2];
            bf[2 * p + 1][1] = br[3];
        }
#pragma unroll
        for (int mt = 0; mt < 2; mt++)
#pragma unroll
            for (int nt = 0; nt < 10; nt++)
                mma_f16(acc[mt][nt], af[mt], bf[nt]);
    }

    float rs_a[2] = {0.f, 0.f}, rs_b[2] = {0.f, 0.f};
#pragma unroll
    for (int mt = 0; mt < 2; mt++) {
#pragma unroll
        for (int nt = 0; nt < 10; nt++) {
            int col = nt * 8 + 2 * (lane & 3);
            float e0 = (col     < T_) ? __expf(acc[mt][nt][0] * SCALE_) : 0.f;
            float e1 = (col + 1 < T_) ? __expf(acc[mt][nt][1] * SCALE_) : 0.f;
            float e2 = (col     < T_) ? __expf(acc[mt][nt][2] * SCALE_) : 0.f;
            float e3 = (col + 1 < T_) ? __expf(acc[mt][nt][3] * SCALE_) : 0.f;
            acc[mt][nt][0] = e0; acc[mt][nt][1] = e1;
            acc[mt][nt][2] = e2; acc[mt][nt][3] = e3;
            rs_a[mt] += e0 + e1;
            rs_b[mt] += e2 + e3;
        }
        rs_a[mt] += __shfl_xor_sync(0xffffffffu, rs_a[mt], 1);
        rs_a[mt] += __shfl_xor_sync(0xffffffffu, rs_a[mt], 2);
        rs_b[mt] += __shfl_xor_sync(0xffffffffu, rs_b[mt], 1);
        rs_b[mt] += __shfl_xor_sync(0xffffffffu, rs_b[mt], 2);
    }
    float inv_a[2] = {1.f / rs_a[0], 1.f / rs_a[1]};
    float inv_b[2] = {1.f / rs_b[0], 1.f / rs_b[1]};

#pragma unroll
    for (int nt = 0; nt < 10; nt++) {
        float cs0 = acc[0][nt][0] * inv_a[0] + acc[0][nt][2] * inv_b[0]
                  + acc[1][nt][0] * inv_a[1] + acc[1][nt][2] * inv_b[1];
        float cs1 = acc[0][nt][1] * inv_a[0] + acc[0][nt][3] * inv_b[0]
                  + acc[1][nt][1] * inv_a[1] + acc[1][nt][3] * inv_b[1];
#pragma unroll
        for (int o = 4; o <= 16; o <<= 1) {
            cs0 += __shfl_xor_sync(0xffffffffu, cs0, o);
            cs1 += __shfl_xor_sync(0xffffffffu, cs1, o);
        }
        if (lane < 4) {
            int col = nt * 8 + 2 * lane;
            tpw[wid][col]     = cs0;
            tpw[wid][col + 1] = cs1;
        }
    }
    __syncthreads();
    if (tid < T_) {
        int lin = (b * H_ + h) * SCHUNK_ + blockIdx.x;
        tokpart[(size_t)lin * T_ + tid] = tpw[0][tid] + tpw[1][tid] + tpw[2][tid] + tpw[3][tid];
    }
}

// ---------------- token score reduce + top-k ----------------
__global__ void tok_reduce_k(const float* __restrict__ tokpart, float* __restrict__ scores)
{
    int idx = blockIdx.x * blockDim.x + threadIdx.x;
    if (idx >= B_ * T_) return;
    int b = idx / T_, t = idx % T_;
    float sum = 0.f;
    for (int h = 0; h < H_; h++)
        for (int c = 0; c < SCHUNK_; c++)
            sum += tokpart[(size_t)((b * H_ + h) * SCHUNK_ + c) * T_ + t];
    scores[idx] = sum * (1.f / (float)(H_ * S_));
}

__global__ void tok_topk_k(const float* __restrict__ scores, int* __restrict__ mask)
{
    int b = blockIdx.x, tid = threadIdx.x;
    __shared__ float sc[T_];
    if (tid < T_) sc[tid] = scores[b * T_ + tid];
    __syncthreads();
    if (tid < T_) {
        float v = sc[tid];
        int rank = 0;
        for (int j = 0; j < T_; j++) {
            float u = sc[j];
            rank += (int)((u > v) || (u == v && j < tid));
        }
        mask[b * T_ + tid] = (rank < KTOK_) ? 1 : 0;
    }
}

// ---------------- pos partial reduce + top-k ----------------
__global__ void pos_reduce_k(const float* __restrict__ posp, float* __restrict__ scores)
{
    int idx = blockIdx.x * blockDim.x + threadIdx.x;
    if (idx >= B_ * S_) return;
    int b = idx / S_, s = idx % S_;
    float sum = 0.f;
#pragma unroll
    for (int h = 0; h < H_; h++) sum += posp[(size_t)(b * H_ + h) * S_ + s];
    scores[idx] = sum * (1.f / (float)H_);
}

__global__ __launch_bounds__(256) void pos_topk_k(const float* __restrict__ scores, int* __restrict__ mask)
{
    const int b = blockIdx.y;
    __shared__ float sc[S_];
    for (int i = threadIdx.x; i < S_; i += 256) sc[i] = scores[b * S_ + i];
    __syncthreads();
    const int i = blockIdx.x * 256 + threadIdx.x;
    float v = sc[i];
    int rank = 0;
    for (int j = 0; j < S_; j++) {
        float u = sc[j];
        rank += (int)((u > v) || (u == v && j < i));
    }
    mask[b * S_ + i] = (rank < KPOS_) ? 1 : 0;
}

// ---------------- cross-frame K/V mixing ----------------
__global__ void kvmix_k(const float* __restrict__ kin, const float* __restrict__ vin,
                        const int* __restrict__ tokmask,
                        float* __restrict__ k2, float* __restrict__ v2)
{
    int idx = blockIdx.x * blockDim.x + threadIdx.x;
    if (idx >= T_ * HD_) return;
    int t = idx / HD_;
    int c = idx % HD_;
    float kv[B_], vv[B_];
    float ksum = 0.f, vsum = 0.f;
#pragma unroll
    for (int b = 0; b < B_; b++) {
        size_t off = ((size_t)(b * T_) + t) * HD_ + c;
        kv[b] = kin[off];
        vv[b] = vin[off];
        ksum += kv[b];
        vsum += vv[b];
    }
#pragma unroll
    for (int b = 0; b < B_; b++) {
        float tm = tokmask[b * T_ + t] ? STRENGTH_ : 0.f;
        size_t off = ((size_t)(b * T_) + t) * HD_ + c;
        float x  = kv[b];
        float mo = (ksum - x) * (1.f / (float)(B_ - 1));
        float mixed = ALPHA_ * x + (1.f - ALPHA_) * mo;
        k2[off] = x + tm * (mixed - x);
        x  = vv[b];
        mo = (vsum - x) * (1.f / (float)(B_ - 1));
        mixed = ALPHA_ * x + (1.f - ALPHA_) * mo;
        v2[off] = x + tm * (mixed - x);
    }
}

// ====================================================================
//  attention pass 2 : QK (pos partials) + QK2 softmax + P·V, fp16 ctx out
// ====================================================================
#define VP_  72
#define PP_  88
#define A2_QS 0
#define A2_KS (A2_QS + 128 * QP_ * 2)
#define A2_LS (A2_KS + 64 * KP2_ * 2)
#define A2_VS (A2_LS + 64 * KP2_ * 2)
#define A2_PS (A2_VS + TP_ * VP_ * 2)
#define A2_MS (A2_PS + 128 * PP_ * 2)
#define A2_SMEM (A2_MS + TP_ * 4)

__global__ __launch_bounds__(128) void attn2_k(
    const __half* __restrict__ q, const float* __restrict__ kk,
    const float* __restrict__ k2, const float* __restrict__ v2,
    const int* __restrict__ tokmask,
    float* __restrict__ posp, __half* __restrict__ ctx)
{
    extern __shared__ char dsm[];
    __half* Qs = (__half*)(dsm + A2_QS);
    __half* Ks = (__half*)(dsm + A2_KS);
    __half* Ls = (__half*)(dsm + A2_LS);
    __half* Vs = (__half*)(dsm + A2_VS);
    __half* Ph = (__half*)(dsm + A2_PS);
    float*  Ms = (float*)(dsm + A2_MS);

    const int b = blockIdx.z, h = blockIdx.y;
    const int tid = threadIdx.x;
    const int wid = tid >> 5, lane = tid & 31;
    const int bm0 = blockIdx.x * 128;

#pragma unroll
    for (int i = 0; i < 8; i++) {
        int f = tid + i * 128;
        int row = f >> 3, c8 = (f & 7) * 8;
        uint4 v = *(const uint4*)(q + ((size_t)(b * S_) + bm0 + row) * HD_ + h * D_ + c8);
        *(uint4*)&Qs[row * QP_ + c8] = v;
    }
    for (int f = tid; f < 64 * KP2_ / 2; f += 128) { ((uint32_t*)Ks)[f] = 0; ((uint32_t*)Ls)[f] = 0; }
    for (int f = tid; f < TP_ * VP_ / 2; f += 128) ((uint32_t*)Vs)[f] = 0;
    if (tid < TP_) Ms[tid] = (tid < T_) ? (float)tokmask[b * T_ + tid] : 0.f;
    __syncthreads();
    for (int f = tid; f < T_ * 16; f += 128) {
        int t = f >> 4, d4 = (f & 15) * 4;
        float4 kv = *(const float4*)(kk + ((size_t)(b * T_) + t) * HD_ + h * D_ + d4);
        Ks[(d4 + 0) * KP2_ + t] = __float2half_rn(kv.x);
        Ks[(d4 + 1) * KP2_ + t] = __float2half_rn(kv.y);
        Ks[(d4 + 2) * KP2_ + t] = __float2half_rn(kv.z);
        Ks[(d4 + 3) * KP2_ + t] = __float2half_rn(kv.w);
        float4 lv = *(const float4*)(k2 + ((size_t)(b * T_) + t) * HD_ + h * D_ + d4);
        Ls[(d4 + 0) * KP2_ + t] = __float2half_rn(lv.x);
        Ls[(d4 + 1) * KP2_ + t] = __float2half_rn(lv.y);
        Ls[(d4 + 2) * KP2_ + t] = __float2half_rn(lv.z);
        Ls[(d4 + 3) * KP2_ + t] = __float2half_rn(lv.w);
        float4 vv = *(const float4*)(v2 + ((size_t)(b * T_) + t) * HD_ + h * D_ + d4);
        uint2 av; av.x = pack_h2(vv.x, vv.y); av.y = pack_h2(vv.z, vv.w);
        *(uint2*)&Vs[t * VP_ + d4] = av;
    }
    __syncthreads();

    const int ltile = lane >> 3, lrit = lane & 7;
    const int a_m  = wid * 32 + (ltile & 1) * 8 + lrit;
    const int a_kc = (ltile >> 1) * 8;
    const int b_k  = (ltile & 1) * 8 + lrit;
    const int b_n  = (ltile >> 1) * 8;

    // ---- pass A: logits = Q K^T -> pos partials ----
    {
        float acc[2][10][4];
#pragma unroll
        for (int mt = 0; mt < 2; mt++)
#pragma unroll
            for (int nt = 0; nt < 10; nt++)
#pragma unroll
                for (int r = 0; r < 4; r++) acc[mt][nt][r] = 0.f;

#pragma unroll
        for (int kkk = 0; kkk < 64; kkk += 16) {
            uint32_t af[2][4], bf[10][2];
#pragma unroll
            for (int mt = 0; mt < 2; mt++)
                ldmx4(af[mt], &Qs[(a_m + mt * 16) * QP_ + kkk + a_kc]);
#pragma unroll
            for (int p = 0; p < 5; p++) {
                uint32_t br[4];
                ldmx4t(br, &Ks[(kkk + b_k) * KP2_ + b_n + p * 16]);
                bf[2 * p][0]     = br[0];
                bf[2 * p][1]     = br[1];
                bf[2 * p + 1][0] = br[2];
                bf[2 * p + 1][1] = br[3];
            }
#pragma unroll
            for (int mt = 0; mt < 2; mt++)
#pragma unroll
                for (int nt = 0; nt < 10; nt++)
                    mma_f16(acc[mt][nt], af[mt], bf[nt]);
        }

        float rs_a[2] = {0.f, 0.f}, rs_b[2] = {0.f, 0.f};
        float ms_a[2] = {0.f, 0.f}, ms_b[2] = {0.f, 0.f};
#pragma unroll
        for (int mt = 0; mt < 2; mt++) {
#pragma unroll
            for (int nt = 0; nt < 10; nt++) {
                int col = nt * 8 + 2 * (lane & 3);
                float m0 = Ms[col], m1 = Ms[col + 1];
                float e0 = (col     < T_) ? __expf(acc[mt][nt][0] * SCALE_) : 0.f;
                float e1 = (col + 1 < T_) ? __expf(acc[mt][nt][1] * SCALE_) : 0.f;
                float e2 = (col     < T_) ? __expf(acc[mt][nt][2] * SCALE_) : 0.f;
                float e3 = (col + 1 < T_) ? __expf(acc[mt][nt][3] * SCALE_) : 0.f;
                rs_a[mt] += e0 + e1;
                rs_b[mt] += e2 + e3;
                ms_a[mt] += e0 * m0 + e1 * m1;
                ms_b[mt] += e2 * m0 + e3 * m1;
            }
            rs_a[mt] += __shfl_xor_sync(0xffffffffu, rs_a[mt], 1);
            rs_a[mt] += __shfl_xor_sync(0xffffffffu, rs_a[mt], 2);
            rs_b[mt] += __shfl_xor_sync(0xffffffffu, rs_b[mt], 1);
            rs_b[mt] += __shfl_xor_sync(0xffffffffu, rs_b[mt], 2);
            ms_a[mt] += __shfl_xor_sync(0xffffffffu, ms_a[mt], 1);
            ms_a[mt] += __shfl_xor_sync(0xffffffffu, ms_a[mt], 2);
            ms_b[mt] += __shfl_xor_sync(0xffffffffu, ms_b[mt], 1);
            ms_b[mt] += __shfl_xor_sync(0xffffffffu, ms_b[mt], 2);
        }
        if ((lane & 3) == 0) {
            const size_t pb2 = (size_t)(b * H_ + h) * S_ + bm0;
#pragma unroll
            for (int mt = 0; mt < 2; mt++) {
                int r = wid * 32 + mt * 16 + (lane >> 2);
                posp[pb2 + r]     = ms_a[mt] / rs_a[mt];
                posp[pb2 + r + 8] = ms_b[mt] / rs_b[mt];
            }
        }
    }

    // ---- pass B: logits2 = Q K2^T -> softmax -> P fp16 -> P V ----
    float acc[2][10][4];
#pragma unroll
    for (int mt = 0; mt < 2; mt++)
#pragma unroll
        for (int nt = 0; nt < 10; nt++)
#pragma unroll
            for (int r = 0; r < 4; r++) acc[mt][nt][r] = 0.f;

#pragma unroll
    for (int kkk = 0; kkk < 64; kkk += 16) {
        uint32_t af[2][4], bf[10][2];
#pragma unroll
        for (int mt = 0; mt < 2; mt++)
            ldmx4(af[mt], &Qs[(a_m + mt * 16) * QP_ + kkk + a_kc]);
#pragma unroll
        for (int p = 0; p < 5; p++) {
            uint32_t br[4];
            ldmx4t(br, &Ls[(kkk + b_k) * KP2_ + b_n + p * 16]);
            bf[2 * p][0]     = br[0];
            bf[2 * p][1]     = br[1];
            bf[2 * p + 1][0] = br[2];
            bf[2 * p + 1][1] = br[3];
        }
#pragma unroll
        for (int mt = 0; mt < 2; mt++)
#pragma unroll
            for (int nt = 0; nt < 10; nt++)
                mma_f16(acc[mt][nt], af[mt], bf[nt]);
    }

    float rs_a[2] = {0.f, 0.f}, rs_b[2] = {0.f, 0.f};
#pragma unroll
    for (int mt = 0; mt < 2; mt++) {
#pragma unroll
        for (int nt = 0; nt < 10; nt++) {
            int col = nt * 8 + 2 * (lane & 3);
            float e0 = (col     < T_) ? __expf(acc[mt][nt][0] * SCALE_) : 0.f;
            float e1 = (col + 1 < T_) ? __expf(acc[mt][nt][1] * SCALE_) : 0.f;
            float e2 = (col     < T_) ? __expf(acc[mt][nt][2] * SCALE_) : 0.f;
            float e3 = (col + 1 < T_) ? __expf(acc[mt][nt][3] * SCALE_) : 0.f;
            acc[mt][nt][0] = e0; acc[mt][nt][1] = e1;
            acc[mt][nt][2] = e2; acc[mt][nt][3] = e3;
            rs_a[mt] += e0 + e1;
            rs_b[mt] += e2 + e3;
        }
        rs_a[mt] += __shfl_xor_sync(0xffffffffu, rs_a[mt], 1);
        rs_a[mt] += __shfl_xor_sync(0xffffffffu, rs_a[mt], 2);
        rs_b[mt] += __shfl_xor_sync(0xffffffffu, rs_b[mt], 1);
        rs_b[mt] += __shfl_xor_sync(0xffffffffu, rs_b[mt], 2);
    }
    float inv_a[2] = {1.f / rs_a[0], 1.f / rs_a[1]};
    float inv_b[2] = {1.f / rs_b[0], 1.f / rs_b[1]};

#pragma unroll
    for (int mt = 0; mt < 2; mt++) {
        int r = wid * 32 + mt * 16 + (lane >> 2);
#pragma unroll
        for (int nt = 0; nt < 10; nt++) {
            int col = nt * 8 + 2 * (lane & 3);
            *(uint32_t*)&Ph[r * PP_ + col] =
                pack_h2(acc[mt][nt][0] * inv_a[mt], acc[mt][nt][1] * inv_a[mt]);
            *(uint32_t*)&Ph[(r + 8) * PP_ + col] =
                pack_h2(acc[mt][nt][2] * inv_b[mt], acc[mt][nt][3] * inv_b[mt]);
        }
    }
    __syncthreads();

    float acc2[2][8][4];
#pragma unroll
    for (int mt = 0; mt < 2; mt++)
#pragma unroll
        for (int nt = 0; nt < 8; nt++)
#pragma unroll
            for (int r = 0; r < 4; r++) acc2[mt][nt][r] = 0.f;

#pragma unroll
    for (int kkk = 0; kkk < TP_; kkk += 16) {
        uint32_t af[2][4], bf[8][2];
#pragma unroll
        for (int mt = 0; mt < 2; mt++)
            ldmx4(af[mt], &Ph[(a_m + mt * 16) * PP_ + kkk + a_kc]);
#pragma unroll
        for (int p = 0; p < 4; p++) {
            uint32_t br[4];
            ldmx4t(br, &Vs[(kkk + b_k) * VP_ + b_n + p * 16]);
            bf[2 * p][0]     = br[0];
            bf[2 * p][1]     = br[1];
            bf[2 * p + 1][0] = br[2];
            bf[2 * p + 1][1] = br[3];
        }
#pragma unroll
        for (int mt = 0; mt < 2; mt++)
#pragma unroll
            for (int nt = 0; nt < 8; nt++)
                mma_f16(acc2[mt][nt], af[mt], bf[nt]);
    }

#pragma unroll
    for (int mt = 0; mt < 2; mt++) {
        int r = wid * 32 + mt * 16 + (lane >> 2);
#pragma unroll
        for (int nt = 0; nt < 8; nt++) {
            int col = nt * 8 + 2 * (lane & 3);
            *(uint32_t*)(ctx + ((size_t)(b * S_) + bm0 + r) * HD_ + h * D_ + col) =
                pack_h2(acc2[mt][nt][0], acc2[mt][nt][1]);
            *(uint32_t*)(ctx + ((size_t)(b * S_) + bm0 + r + 8) * HD_ + h * D_ + col) =
                pack_h2(acc2[mt][nt][2], acc2[mt][nt][3]);
        }
    }
}

// ---------------- fused batch-sum + patch injection on fp16 ctx ----------------
__global__ __launch_bounds__(256) void inject_fused_k(
    __half* __restrict__ ctx, const int* __restrict__ posmask)
{
    const int i4 = blockIdx.x * 256 + threadIdx.x;   // group of 4 halves
    if (i4 >= S_ * HD_ / 4) return;
    const size_t base = (size_t)i4 * 4;
    const int s = (int)(base / HD_);

    float v[B_][4];
    float sum[4] = {0.f, 0.f, 0.f, 0.f};
#pragma unroll
    for (int b = 0; b < B_; b++) {
        uint2 u = *(const uint2*)(ctx + (size_t)b * S_ * HD_ + base);
        float2 f0 = __half22float2(*(__half2*)&u.x);
        float2 f1 = __half22float2(*(__half2*)&u.y);
        v[b][0] = f0.x; v[b][1] = f0.y; v[b][2] = f1.x; v[b][3] = f1.y;
#pragma unroll
        for (int j = 0; j < 4; j++) sum[j] += v[b][j];
    }
    const float c7 = 1.f / (float)(B_ - 1);
#pragma unroll
    for (int b = 0; b < B_; b++) {
        if (posmask[b * S_ + s]) {
            float o[4];
#pragma unroll
            for (int j = 0; j < 4; j++)
                o[j] = v[b][j] + WINJ_ * ((sum[j] - v[b][j]) * c7 - v[b][j]);
            uint2 u;
            u.x = pack_h2(o[0], o[1]);
            u.y = pack_h2(o[2], o[3]);
            *(uint2*)(ctx + (size_t)b * S_ * HD_ + base) = u;
        }
    }
}

// ---------------- launch ----------------
extern "C" void kernel_launch(void* const* d_in, const int* in_sizes, int n_in,
                              void* d_out, int out_size)
{
    (void)in_sizes; (void)n_in; (void)out_size;
    const float* X  = (const float*)d_in[0];
    const float* E  = (const float*)d_in[1];
    const float* Wq = (const float*)d_in[2];
    const float* Wk = (const float*)d_in[3];
    const float* Wv = (const float*)d_in[4];
    const float* Wo = (const float*)d_in[5];
    const float* bo = (const float*)d_in[6];
    float* out = (float*)d_out;

    __half *q, *ctx;
    float *k, *v, *k2, *v2, *posp, *tokpart, *tokscores, *posscores;
    int *tokmask, *posmask;
    cudaGetSymbolAddress((void**)&q,        g_q);
    cudaGetSymbolAddress((void**)&k,        g_k);
    cudaGetSymbolAddress((void**)&v,        g_v);
    cudaGetSymbolAddress((void**)&k2,       g_k2);
    cudaGetSymbolAddress((void**)&v2,       g_v2);
    cudaGetSymbolAddress((void**)&posp,     g_posp);
    cudaGetSymbolAddress((void**)&tokpart,  g_tokpart);
    cudaGetSymbolAddress((void**)&tokscores,g_tokscores);
    cudaGetSymbolAddress((void**)&tokmask,  g_tokmask);
    cudaGetSymbolAddress((void**)&posscores,g_posscores);
    cudaGetSymbolAddress((void**)&posmask,  g_posmask);
    cudaGetSymbolAddress((void**)&ctx,      g_ctx);

    cudaFuncSetAttribute(attn2_k, cudaFuncAttributeMaxDynamicSharedMemorySize, A2_SMEM);

    // 1. projections (Q -> fp16; K,V -> fp32)
    h16gemm_k<1><<<dim3(HD_ / 128, (B_ * S_) / 128), 256>>>(X, Wq, q, B_ * S_, HD_, C_);
    h16gemm_k<0><<<dim3(HD_ / 128, (B_ * T_ + 127) / 128), 256>>>(E, Wk, k, B_ * T_, HD_, CE_);
    h16gemm_k<0><<<dim3(HD_ / 128, (B_ * T_ + 127) / 128), 256>>>(E, Wv, v, B_ * T_, HD_, CE_);

    // 2. first attention pass -> token partials
    attn1_k<<<dim3(SCHUNK_, H_, B_), 128>>>(q, k, tokpart);
    tok_reduce_k<<<(B_ * T_ + 255) / 256, 256>>>(tokpart, tokscores);
    tok_topk_k<<<B_, 128>>>(tokscores, tokmask);

    // 3. cross-frame K/V mixing
    kvmix_k<<<(T_ * HD_ + 255) / 256, 256>>>(k, v, tokmask, k2, v2);

    // 4. second attention pass -> pos partials + fp16 context
    attn2_k<<<dim3(SCHUNK_, H_, B_), 128, A2_SMEM>>>(q, k, k2, v2, tokmask, posp, ctx);

    // 5. position scores + top-k
    pos_reduce_k<<<(B_ * S_ + 255) / 256, 256>>>(posp, posscores);
    pos_topk_k<<<dim3(S_ / 256, B_), 256>>>(posscores, posmask);

    // 6. fused batch-sum + patch injection (fp16)
    inject_fused_k<<<(S_ * HD_ / 4 + 255) / 256, 256>>>(ctx, posmask);

    // 7. output projection + bias + residual (fp16 A)
    h16gemmA16_k<<<dim3(HD_ / 128, (B_ * S_) / 128), 256>>>(ctx, Wo, out, B_ * S_, HD_, C_, bo, X);
}